// round 8
// baseline (speedup 1.0000x reference)
#include <cuda_runtime.h>
#include <cooperative_groups.h>
#include <math.h>

namespace cg = cooperative_groups;

#define SEQ   4096
#define BATCH 16
#define DIM   1024
#define HID   512
#define LL    32
#define BD    (BATCH*DIM)   // 16384

// ---------------- scratch ---------------------------------------------------------
__device__ float g_partial[32][BD];
__device__ float g_ctx[BATCH][DIM];
__device__ float g_sp_h[BATCH][HID];
__device__ float g_ctx_part[BATCH][HID];
__device__ float g_hist_pre[2][LL*BATCH][HID];
__device__ float g_pool_feat[2][BATCH][DIM];
__device__ float g_scores[2][LL][BATCH];
__device__ float g_spanlg[BATCH][3];
__device__ float g_sw[BATCH][2];
__device__ float g_fused_raw[BATCH][DIM];
__device__ float g_fg[BATCH][DIM];

__device__ __forceinline__ float gelu_exact(float x){
    return 0.5f * x * (1.0f + erff(x * 0.70710678118654752440f));
}

// ---------------- K1: partial column sums over 128-row s-chunks -------------------
__global__ void __launch_bounds__(256) k_partial(const float* __restrict__ f){
    int col = blockIdx.x * 256 + threadIdx.x;
    int sy  = blockIdx.y;
    const float* p = f + (size_t)sy * 128 * BD + col;
    float s = 0.f;
    #pragma unroll 8
    for (int i = 0; i < 128; i++) s += p[(size_t)i * BD];
    g_partial[sy][col] = s;
}

// ---------------- K2: hist GEMM (M=512,N=512,K=1024) x2 pools ---------------------
__global__ void __launch_bounds__(256) k_histgemm(const float* __restrict__ f,
                                                  const float* __restrict__ w_rs1){
    __shared__ __align__(16) float As[16][68];
    __shared__ __align__(16) float Bs[16][68];
    int pool = blockIdx.z;
    int m0 = blockIdx.y * 64, n0 = blockIdx.x * 64;
    int t = threadIdx.x;
    int lrow = t >> 2;
    int kq   = (t & 3) * 4;

    int m = m0 + lrow;
    size_t aoff = (pool == 0)
        ? (size_t)4064 * BD + (size_t)m * 1024
        : (size_t)(m >> 4) * 128 * BD + (size_t)(m & 15) * 1024;
    const float* aptr = f + aoff;
    const float* bptr = w_rs1 + (size_t)(n0 + lrow) * 2048;

    int tx = t & 15, ty = t >> 4;
    float acc[4][4] = {};

    for (int k0 = 0; k0 < 1024; k0 += 16){
        float4 av = *(const float4*)(aptr + k0 + kq);
        float4 bv = *(const float4*)(bptr + k0 + kq);
        __syncthreads();
        As[kq+0][lrow]=av.x; As[kq+1][lrow]=av.y; As[kq+2][lrow]=av.z; As[kq+3][lrow]=av.w;
        Bs[kq+0][lrow]=bv.x; Bs[kq+1][lrow]=bv.y; Bs[kq+2][lrow]=bv.z; Bs[kq+3][lrow]=bv.w;
        __syncthreads();
        #pragma unroll
        for (int kk = 0; kk < 16; kk++){
            float4 a = *(const float4*)&As[kk][ty*4];
            float4 b = *(const float4*)&Bs[kk][tx*4];
            acc[0][0] += a.x*b.x; acc[0][1] += a.x*b.y; acc[0][2] += a.x*b.z; acc[0][3] += a.x*b.w;
            acc[1][0] += a.y*b.x; acc[1][1] += a.y*b.y; acc[1][2] += a.y*b.z; acc[1][3] += a.y*b.w;
            acc[2][0] += a.z*b.x; acc[2][1] += a.z*b.y; acc[2][2] += a.z*b.z; acc[2][3] += a.z*b.w;
            acc[3][0] += a.w*b.x; acc[3][1] += a.w*b.y; acc[3][2] += a.w*b.z; acc[3][3] += a.w*b.w;
        }
    }
    #pragma unroll
    for (int i = 0; i < 4; i++)
        #pragma unroll
        for (int j = 0; j < 4; j++)
            g_hist_pre[pool][m0 + ty*4 + i][n0 + tx*4 + j] = acc[i][j];
}

// ---------------- K3: fused mid-chain (cooperative, grid 256 x 256) ----------------
// P0 ctxfin | P1 ctx MLPs | P2 scores + span logits | P3 softmax + pool | P4 ff | P5 LN+gate
__global__ void __launch_bounds__(256, 2) k_mid(const float* __restrict__ f,
                                                const float* __restrict__ w_sp1,
                                                const float* __restrict__ b_sp1,
                                                const float* __restrict__ w_sp2,
                                                const float* __restrict__ b_sp2,
                                                const float* __restrict__ w_rs1,
                                                const float* __restrict__ b_rs1,
                                                const float* __restrict__ w_rs2,
                                                const float* __restrict__ b_rs2,
                                                const float* __restrict__ decay_l,
                                                const float* __restrict__ decay_g,
                                                const float* __restrict__ w_ff,
                                                const float* __restrict__ b_ff,
                                                const float* __restrict__ ln_ff_g,
                                                const float* __restrict__ ln_ff_b,
                                                const float* __restrict__ w_gate,
                                                const float* __restrict__ b_gate){
    cg::grid_group grid = cg::this_grid();
    __shared__ __align__(16) float smem[8200];   // 32KB + LN stats
    int bk = blockIdx.x;
    int t = threadIdx.x, warp = t >> 5, lane = t & 31;

    // ---- P0: finalize ctx (blocks 0..63) ----
    if (bk < 64){
        int col = bk * 256 + t;
        float s = 0.f;
        #pragma unroll
        for (int j = 0; j < 32; j++) s += g_partial[j][col];
        g_ctx[col >> 10][col & 1023] = s * (1.0f/4096.0f);
    }
    grid.sync();

    // ---- P1: ctx MLPs (all 256 blocks; 8 batches per half) ----
    {
        int b0 = (bk >> 7) * 8;
        float (*ctxs)[DIM] = (float(*)[DIM])smem;
        for (int idx = t; idx < 8 * DIM; idx += 256)
            ctxs[idx >> 10][idx & 1023] = g_ctx[b0 + (idx >> 10)][idx & 1023];
        __syncthreads();

        int slot = (bk & 127) * 8 + warp;
        const float4* w4 = (slot < 512)
            ? (const float4*)(w_sp1 + (size_t)slot * 1024)
            : (const float4*)(w_rs1 + (size_t)(slot - 512) * 2048 + 1024);

        float4 wreg[8];
        #pragma unroll
        for (int ii = 0; ii < 8; ii++) wreg[ii] = w4[lane + ii*32];

        float acc[8] = {};
        #pragma unroll
        for (int ii = 0; ii < 8; ii++){
            int i = lane + ii*32;
            float4 w = wreg[ii];
            #pragma unroll
            for (int bb = 0; bb < 8; bb++){
                float4 c = *(const float4*)&ctxs[bb][i*4];
                acc[bb] += w.x*c.x + w.y*c.y + w.z*c.z + w.w*c.w;
            }
        }
        #pragma unroll
        for (int bb = 0; bb < 8; bb++){
            float s = acc[bb];
            #pragma unroll
            for (int o = 16; o > 0; o >>= 1) s += __shfl_xor_sync(0xffffffffu, s, o);
            if (lane == 0){
                if (slot < 512) g_sp_h[b0 + bb][slot] = gelu_exact(s + b_sp1[slot]);
                else            g_ctx_part[b0 + bb][slot - 512] = s + b_rs1[slot - 512];
            }
        }
        __syncthreads();
    }
    grid.sync();

    // ---- P2: relevance scores (blocks 0..127) + span logits (blocks 128..133) ----
    if (bk < 128){
        int group = bk >> 2;            // 0..31
        int b = group & 15, pool = group >> 4;
        int l = (bk & 3) * 8 + warp;    // 0..31
        const float4* hp = (const float4*)&g_hist_pre[pool][l*16 + b][0];
        const float4* cp = (const float4*)&g_ctx_part[b][0];
        const float4* wp = (const float4*)w_rs2;
        float s = 0.f;
        #pragma unroll
        for (int i = lane; i < 128; i += 32){
            float4 h = hp[i], c = cp[i], w = wp[i];
            s += gelu_exact(h.x + c.x) * w.x + gelu_exact(h.y + c.y) * w.y
               + gelu_exact(h.z + c.z) * w.z + gelu_exact(h.w + c.w) * w.w;
        }
        #pragma unroll
        for (int o = 16; o > 0; o >>= 1) s += __shfl_xor_sync(0xffffffffu, s, o);
        if (lane == 0) g_scores[pool][l][b] = s + b_rs2[0];
    } else if (bk < 134){
        int task = (bk - 128) * 8 + warp;   // 0..47
        int b = task / 3, j = task - b * 3;
        const float4* sp = (const float4*)&g_sp_h[b][0];
        const float4* wp = (const float4*)(w_sp2 + j*HID);
        float s = 0.f;
        #pragma unroll
        for (int i = lane; i < 128; i += 32){
            float4 a = sp[i], w = wp[i];
            s += a.x*w.x + a.y*w.y + a.z*w.z + a.w*w.w;
        }
        #pragma unroll
        for (int o = 16; o > 0; o >>= 1) s += __shfl_xor_sync(0xffffffffu, s, o);
        if (lane == 0) g_spanlg[b][j] = s + b_sp2[j];
    }
    grid.sync();

    // ---- P3: decay softmax + pooled feature (blocks 0..127) + span softmax ----
    if (bk < 128){
        int group = bk >> 2;
        int b = group & 15, pool = group >> 4;
        float* wgt = smem;
        if (warp == 0){
            float dec = (pool == 0) ? decay_l[0] : decay_g[0];
            float tv = g_scores[pool][lane][b] + logf(powf(dec, (float)(LL - 1 - lane)) + 1e-8f);
            float mx = tv;
            #pragma unroll
            for (int o = 16; o > 0; o >>= 1) mx = fmaxf(mx, __shfl_xor_sync(0xffffffffu, mx, o));
            float e = expf(tv - mx);
            float ssum = e;
            #pragma unroll
            for (int o = 16; o > 0; o >>= 1) ssum += __shfl_xor_sync(0xffffffffu, ssum, o);
            wgt[lane] = e / ssum;
        }
        __syncthreads();
        int d = (bk & 3) * 256 + t;
        float acc = 0.f;
        #pragma unroll
        for (int l = 0; l < LL; l++){
            size_t off = (pool == 0) ? (size_t)(4064 + l) * BD : (size_t)l * 128 * BD;
            acc += wgt[l] * f[off + (size_t)b*1024 + d];
        }
        g_pool_feat[pool][b][d] = acc;
        __syncthreads();
    } else if (bk == 128 && t < BATCH){
        float a = g_spanlg[t][0], b2 = g_spanlg[t][1], c = g_spanlg[t][2];
        float m = fmaxf(a, fmaxf(b2, c));
        float ea = expf(a-m), eb = expf(b2-m), ec = expf(c-m);
        float inv = 1.0f / (ea + eb + ec);
        g_sw[t][0] = eb*inv; g_sw[t][1] = ec*inv;
    }
    grid.sync();

    // ---- P4: fused MLP GEMV (all 256 blocks: 16 slots x 4 batches each) ----
    {
        int b0 = (bk >> 6) * 4;
        float (*comb)[2*DIM] = (float(*)[2*DIM])smem;
        for (int idx = t; idx < 4 * 2 * DIM; idx += 256){
            int bb = idx >> 11, k = idx & 2047;
            comb[bb][k] = (k < DIM) ? g_pool_feat[0][b0+bb][k] * g_sw[b0+bb][0]
                                    : g_pool_feat[1][b0+bb][k-DIM] * g_sw[b0+bb][1];
        }
        __syncthreads();

        int slot0 = (bk & 63) * 16 + warp * 2;
        #pragma unroll
        for (int ss = 0; ss < 2; ss++){
            int slot = slot0 + ss;
            const float4* w4 = (const float4*)(w_ff + (size_t)slot * 2048);
            float acc[4] = {};
            #pragma unroll
            for (int half = 0; half < 2; half++){
                float4 wreg[8];
                #pragma unroll
                for (int ii = 0; ii < 8; ii++) wreg[ii] = w4[lane + (half*8 + ii)*32];
                #pragma unroll
                for (int ii = 0; ii < 8; ii++){
                    int i = lane + (half*8 + ii)*32;
                    float4 w = wreg[ii];
                    #pragma unroll
                    for (int bb = 0; bb < 4; bb++){
                        float4 c = *(const float4*)&comb[bb][i*4];
                        acc[bb] += w.x*c.x + w.y*c.y + w.z*c.z + w.w*c.w;
                    }
                }
            }
            #pragma unroll
            for (int bb = 0; bb < 4; bb++){
                float s = acc[bb];
                #pragma unroll
                for (int o = 16; o > 0; o >>= 1) s += __shfl_xor_sync(0xffffffffu, s, o);
                if (lane == 0) g_fused_raw[b0+bb][slot] = gelu_exact(s + b_ff[slot]);
            }
        }
        __syncthreads();
    }
    grid.sync();

    // ---- P5: LN(fused_raw) + gate GEMV + fg (all 256 blocks) ----
    {
        int b0 = (bk >> 6) * 4;
        float (*fr)[DIM] = (float(*)[DIM])smem;
        float* mu_s = &smem[4096];
        float* rstd_s = &smem[4100];
        for (int idx = t; idx < 4 * DIM; idx += 256)
            fr[idx >> 10][idx & 1023] = g_fused_raw[b0 + (idx >> 10)][idx & 1023];
        __syncthreads();

        if (warp < 4){
            float sum = 0.f, ss = 0.f;
            #pragma unroll
            for (int i = lane; i < 256; i += 32){
                float4 v = *(const float4*)&fr[warp][i*4];
                sum += v.x + v.y + v.z + v.w;
                ss  += v.x*v.x + v.y*v.y + v.z*v.z + v.w*v.w;
            }
            #pragma unroll
            for (int o = 16; o > 0; o >>= 1){
                sum += __shfl_xor_sync(0xffffffffu, sum, o);
                ss  += __shfl_xor_sync(0xffffffffu, ss, o);
            }
            if (lane == 0){
                float mu = sum * (1.0f/1024.0f);
                float var = ss * (1.0f/1024.0f) - mu*mu;
                mu_s[warp] = mu; rstd_s[warp] = rsqrtf(var + 1e-5f);
            }
        }
        __syncthreads();

        for (int idx = t; idx < 4 * DIM; idx += 256){
            int bb = idx >> 10, k = idx & 1023;
            fr[bb][k] = (fr[bb][k] - mu_s[bb]) * rstd_s[bb] * ln_ff_g[k] + ln_ff_b[k];
        }
        __syncthreads();

        int slot0 = (bk & 63) * 16 + warp * 2;
        #pragma unroll
        for (int ss = 0; ss < 2; ss++){
            int slot = slot0 + ss;
            const float4* w4 = (const float4*)(w_gate + (size_t)slot * 1024);
            float4 wreg[8];
            #pragma unroll
            for (int ii = 0; ii < 8; ii++) wreg[ii] = w4[lane + ii*32];
            float acc[4] = {};
            #pragma unroll
            for (int ii = 0; ii < 8; ii++){
                int i = lane + ii*32;
                float4 w = wreg[ii];
                #pragma unroll
                for (int bb = 0; bb < 4; bb++){
                    float4 c = *(const float4*)&fr[bb][i*4];
                    acc[bb] += w.x*c.x + w.y*c.y + w.z*c.z + w.w*c.w;
                }
            }
            #pragma unroll
            for (int bb = 0; bb < 4; bb++){
                float s = acc[bb];
                #pragma unroll
                for (int o = 16; o > 0; o >>= 1) s += __shfl_xor_sync(0xffffffffu, s, o);
                if (lane == 0){
                    float gate = 1.0f / (1.0f + expf(-(s + b_gate[slot])));
                    g_fg[b0+bb][slot] = fr[bb][slot] * gate;
                }
            }
        }
    }
}

// ---------------- K4: big pass — output = LN(features + fg[b]) ----------------------
__global__ void __launch_bounds__(256) k_bigln(const float* __restrict__ f,
                                               const float* __restrict__ ln_g,
                                               const float* __restrict__ ln_b,
                                               float* __restrict__ out){
    int warp = threadIdx.x >> 5, lane = threadIdx.x & 31;
    int row = blockIdx.x * 8 + warp;
    int b = row & 15;
    const float4* x4  = (const float4*)(f + (size_t)row * DIM);
    const float4* fg4 = (const float4*)(&g_fg[b][0]);
    float4 v[8];
    float sum = 0.f, ss = 0.f;
    #pragma unroll
    for (int i = 0; i < 8; i++){
        float4 a = x4[lane + i*32];
        float4 c = fg4[lane + i*32];
        float4 tv;
        tv.x = a.x + c.x; tv.y = a.y + c.y; tv.z = a.z + c.z; tv.w = a.w + c.w;
        v[i] = tv;
        sum += tv.x + tv.y + tv.z + tv.w;
        ss  += tv.x*tv.x + tv.y*tv.y + tv.z*tv.z + tv.w*tv.w;
    }
    #pragma unroll
    for (int o = 16; o > 0; o >>= 1){
        sum += __shfl_xor_sync(0xffffffffu, sum, o);
        ss  += __shfl_xor_sync(0xffffffffu, ss, o);
    }
    float mu = sum * (1.0f/1024.0f);
    float var = ss * (1.0f/1024.0f) - mu*mu;
    float rstd = rsqrtf(var + 1e-5f);
    float4* o4 = (float4*)(out + (size_t)row * DIM);
    const float4* g4 = (const float4*)ln_g;
    const float4* b4 = (const float4*)ln_b;
    #pragma unroll
    for (int i = 0; i < 8; i++){
        float4 g = g4[lane + i*32], be = b4[lane + i*32], tv = v[i], r;
        r.x = (tv.x - mu)*rstd*g.x + be.x;
        r.y = (tv.y - mu)*rstd*g.y + be.y;
        r.z = (tv.z - mu)*rstd*g.z + be.z;
        r.w = (tv.w - mu)*rstd*g.w + be.w;
        o4[lane + i*32] = r;
    }
}

// ---------------- K5: attention weights fill -----------------------------------------
__global__ void k_aw(float* __restrict__ aw){
    aw[blockIdx.x * 256 + threadIdx.x] = 1.0f / 4096.0f;
}

// ---------------- launcher ------------------------------------------------------------
extern "C" void kernel_launch(void* const* d_in, const int* in_sizes, int n_in,
                              void* d_out, int out_size){
    const float* features = (const float*)d_in[0];
    const float* w_sp1    = (const float*)d_in[1];
    const float* b_sp1    = (const float*)d_in[2];
    const float* w_sp2    = (const float*)d_in[3];
    const float* b_sp2    = (const float*)d_in[4];
    const float* w_rs1    = (const float*)d_in[5];
    const float* b_rs1    = (const float*)d_in[6];
    const float* w_rs2    = (const float*)d_in[7];
    const float* b_rs2    = (const float*)d_in[8];
    const float* decay_l  = (const float*)d_in[9];
    const float* decay_g  = (const float*)d_in[10];
    const float* w_ff     = (const float*)d_in[11];
    const float* b_ff     = (const float*)d_in[12];
    const float* ln_ff_g  = (const float*)d_in[13];
    const float* ln_ff_b  = (const float*)d_in[14];
    const float* w_gate   = (const float*)d_in[15];
    const float* b_gate   = (const float*)d_in[16];
    const float* ln_g     = (const float*)d_in[17];
    const float* ln_b     = (const float*)d_in[18];
    float* out = (float*)d_out;
    float* out_aw = out + (size_t)SEQ * BATCH * DIM;

    static cudaStream_t s_side = nullptr;
    static cudaEvent_t ev_fork = nullptr, ev_join = nullptr;
    if (s_side == nullptr){
        cudaStreamCreateWithFlags(&s_side, cudaStreamNonBlocking);
        cudaEventCreateWithFlags(&ev_fork, cudaEventDisableTiming);
        cudaEventCreateWithFlags(&ev_join, cudaEventDisableTiming);
    }

    cudaEventRecord(ev_fork, 0);
    cudaStreamWaitEvent(s_side, ev_fork, 0);
    k_histgemm<<<dim3(8, 8, 2), 256, 0, s_side>>>(features, w_rs1);
    k_aw<<<256, 256, 0, s_side>>>(out_aw);
    cudaEventRecord(ev_join, s_side);

    k_partial<<<dim3(64, 32), 256>>>(features);

    cudaStreamWaitEvent(0, ev_join, 0);

    // cooperative mid-chain
    {
        void* args[] = {
            (void*)&features, (void*)&w_sp1, (void*)&b_sp1, (void*)&w_sp2, (void*)&b_sp2,
            (void*)&w_rs1, (void*)&b_rs1, (void*)&w_rs2, (void*)&b_rs2,
            (void*)&decay_l, (void*)&decay_g, (void*)&w_ff, (void*)&b_ff,
            (void*)&ln_ff_g, (void*)&ln_ff_b, (void*)&w_gate, (void*)&b_gate
        };
        cudaLaunchCooperativeKernel((void*)k_mid, dim3(256), dim3(256), args, 0, 0);
    }

    k_bigln<<<8192, 256>>>(features, ln_g, ln_b, out);
}

// round 9
// speedup vs baseline: 1.0482x; 1.0482x over previous
#include <cuda_runtime.h>
#include <math.h>

#define SEQ   4096
#define BATCH 16
#define DIM   1024
#define HID   512
#define LL    32
#define BD    (BATCH*DIM)   // 16384

// ---------------- scratch ---------------------------------------------------------
__device__ float g_partial[32][BD];
__device__ float g_ctx[BATCH][DIM];
__device__ float g_sp_h[BATCH][HID];
__device__ float g_ctx_part[BATCH][HID];
__device__ float g_hist_pre[2][LL*BATCH][HID];
__device__ float g_pool_feat[2][BATCH][DIM];
__device__ float g_fused_raw[BATCH][DIM];
__device__ float g_fg[BATCH][DIM];

__device__ __forceinline__ float gelu_exact(float x){
    return 0.5f * x * (1.0f + erff(x * 0.70710678118654752440f));
}

// ---------------- K1: partial column sums (primary for ctxfin PDL) -----------------
__global__ void __launch_bounds__(256) k_partial(const float* __restrict__ f){
    int col = blockIdx.x * 256 + threadIdx.x;
    int sy  = blockIdx.y;
    const float* p = f + (size_t)sy * 128 * BD + col;
    float s = 0.f;
    #pragma unroll 8
    for (int i = 0; i < 128; i++) s += p[(size_t)i * BD];
    g_partial[sy][col] = s;
    cudaTriggerProgrammaticLaunchCompletion();
}

// ---------------- K1b: finalize ctx (PDL secondary) --------------------------------
__global__ void __launch_bounds__(256) k_ctxfin(){
    cudaGridDependencySynchronize();
    int col = blockIdx.x * 256 + threadIdx.x;
    float s = 0.f;
    #pragma unroll
    for (int j = 0; j < 32; j++) s += g_partial[j][col];
    g_ctx[col >> 10][col & 1023] = s * (1.0f/4096.0f);
}

// ---------------- K2: hist GEMM (M=512,N=512,K=1024) x2 pools ----------------------
__global__ void __launch_bounds__(256) k_histgemm(const float* __restrict__ f,
                                                  const float* __restrict__ w_rs1){
    __shared__ __align__(16) float As[16][68];
    __shared__ __align__(16) float Bs[16][68];
    int pool = blockIdx.z;
    int m0 = blockIdx.y * 64, n0 = blockIdx.x * 64;
    int t = threadIdx.x;
    int lrow = t >> 2;
    int kq   = (t & 3) * 4;

    int m = m0 + lrow;
    size_t aoff = (pool == 0)
        ? (size_t)4064 * BD + (size_t)m * 1024
        : (size_t)(m >> 4) * 128 * BD + (size_t)(m & 15) * 1024;
    const float* aptr = f + aoff;
    const float* bptr = w_rs1 + (size_t)(n0 + lrow) * 2048;

    int tx = t & 15, ty = t >> 4;
    float acc[4][4] = {};

    for (int k0 = 0; k0 < 1024; k0 += 16){
        float4 av = *(const float4*)(aptr + k0 + kq);
        float4 bv = *(const float4*)(bptr + k0 + kq);
        __syncthreads();
        As[kq+0][lrow]=av.x; As[kq+1][lrow]=av.y; As[kq+2][lrow]=av.z; As[kq+3][lrow]=av.w;
        Bs[kq+0][lrow]=bv.x; Bs[kq+1][lrow]=bv.y; Bs[kq+2][lrow]=bv.z; Bs[kq+3][lrow]=bv.w;
        __syncthreads();
        #pragma unroll
        for (int kk = 0; kk < 16; kk++){
            float4 a = *(const float4*)&As[kk][ty*4];
            float4 b = *(const float4*)&Bs[kk][tx*4];
            acc[0][0] += a.x*b.x; acc[0][1] += a.x*b.y; acc[0][2] += a.x*b.z; acc[0][3] += a.x*b.w;
            acc[1][0] += a.y*b.x; acc[1][1] += a.y*b.y; acc[1][2] += a.y*b.z; acc[1][3] += a.y*b.w;
            acc[2][0] += a.z*b.x; acc[2][1] += a.z*b.y; acc[2][2] += a.z*b.z; acc[2][3] += a.z*b.w;
            acc[3][0] += a.w*b.x; acc[3][1] += a.w*b.y; acc[3][2] += a.w*b.z; acc[3][3] += a.w*b.w;
        }
    }
    #pragma unroll
    for (int i = 0; i < 4; i++)
        #pragma unroll
        for (int j = 0; j < 4; j++)
            g_hist_pre[pool][m0 + ty*4 + i][n0 + tx*4 + j] = acc[i][j];
}

// ---------------- K3: ctx MLPs (primary for scorepool PDL) -------------------------
__global__ void __launch_bounds__(256) k_ctxgemm(const float* __restrict__ w_sp1,
                                                 const float* __restrict__ b_sp1,
                                                 const float* __restrict__ w_rs1,
                                                 const float* __restrict__ b_rs1){
    __shared__ __align__(16) float ctxs[8][DIM];   // 32KB
    int t = threadIdx.x, warp = t >> 5, lane = t & 31;
    int b0 = blockIdx.y * 8;

    for (int idx = t; idx < 8 * DIM; idx += 256)
        ctxs[idx >> 10][idx & 1023] = g_ctx[b0 + (idx >> 10)][idx & 1023];
    __syncthreads();

    int slot = blockIdx.x * 8 + warp;
    const float4* w4 = (slot < 512)
        ? (const float4*)(w_sp1 + (size_t)slot * 1024)
        : (const float4*)(w_rs1 + (size_t)(slot - 512) * 2048 + 1024);

    float4 wreg[8];
    #pragma unroll
    for (int ii = 0; ii < 8; ii++) wreg[ii] = w4[lane + ii*32];

    float acc[8] = {};
    #pragma unroll
    for (int ii = 0; ii < 8; ii++){
        int i = lane + ii*32;
        float4 w = wreg[ii];
        #pragma unroll
        for (int bb = 0; bb < 8; bb++){
            float4 c = *(const float4*)&ctxs[bb][i*4];
            acc[bb] += w.x*c.x + w.y*c.y + w.z*c.z + w.w*c.w;
        }
    }
    #pragma unroll
    for (int bb = 0; bb < 8; bb++){
        float s = acc[bb];
        #pragma unroll
        for (int o = 16; o > 0; o >>= 1) s += __shfl_xor_sync(0xffffffffu, s, o);
        if (lane == 0){
            if (slot < 512) g_sp_h[b0 + bb][slot] = gelu_exact(s + b_sp1[slot]);
            else            g_ctx_part[b0 + bb][slot - 512] = s + b_rs1[slot - 512];
        }
    }
    cudaTriggerProgrammaticLaunchCompletion();
}

// ---------------- K4: scores + softmax + pool (PDL both ways) ----------------------
__global__ void __launch_bounds__(1024) k_scorepool(const float* __restrict__ f,
                                                    const float* __restrict__ w_rs2,
                                                    const float* __restrict__ b_rs2,
                                                    const float* __restrict__ decay_l,
                                                    const float* __restrict__ decay_g){
    int b = blockIdx.x, pool = blockIdx.y;
    int t = threadIdx.x, warp = t >> 5, lane = t & 31;
    __shared__ float wgt[LL];

    // prologue: hist_pre (from fork, long complete) + w_rs2 (input) — safe pre-sync
    const float4* hp = (const float4*)&g_hist_pre[pool][warp*16 + b][0];
    const float4* wp = (const float4*)w_rs2;
    float4 hreg[4], wreg[4];
    #pragma unroll
    for (int ii = 0; ii < 4; ii++){ hreg[ii] = hp[lane + ii*32]; wreg[ii] = wp[lane + ii*32]; }

    cudaGridDependencySynchronize();   // wait: g_ctx_part from ctxgemm

    {
        const float4* cp = (const float4*)&g_ctx_part[b][0];
        float s = 0.f;
        #pragma unroll
        for (int ii = 0; ii < 4; ii++){
            float4 h = hreg[ii], w = wreg[ii], c = cp[lane + ii*32];
            s += gelu_exact(h.x + c.x) * w.x + gelu_exact(h.y + c.y) * w.y
               + gelu_exact(h.z + c.z) * w.z + gelu_exact(h.w + c.w) * w.w;
        }
        #pragma unroll
        for (int o = 16; o > 0; o >>= 1) s += __shfl_xor_sync(0xffffffffu, s, o);
        if (lane == 0) wgt[warp] = s + b_rs2[0];
    }
    __syncthreads();

    if (warp == 0){
        float dec = (pool == 0) ? decay_l[0] : decay_g[0];
        float tv = wgt[lane] + logf(powf(dec, (float)(LL - 1 - lane)) + 1e-8f);
        float mx = tv;
        #pragma unroll
        for (int o = 16; o > 0; o >>= 1) mx = fmaxf(mx, __shfl_xor_sync(0xffffffffu, mx, o));
        float e = expf(tv - mx);
        float ssum = e;
        #pragma unroll
        for (int o = 16; o > 0; o >>= 1) ssum += __shfl_xor_sync(0xffffffffu, ssum, o);
        wgt[lane] = e / ssum;
    }
    __syncthreads();

    int d = t;
    float acc = 0.f;
    #pragma unroll
    for (int l = 0; l < LL; l++){
        size_t off = (pool == 0) ? (size_t)(4064 + l) * BD : (size_t)l * 128 * BD;
        acc += wgt[l] * f[off + (size_t)b*1024 + d];
    }
    g_pool_feat[pool][b][d] = acc;
    cudaTriggerProgrammaticLaunchCompletion();
}

// ---------------- K5: span softmax + fused MLP GEMV (PDL both ways) ----------------
__global__ void __launch_bounds__(256) k_ff(const float* __restrict__ w_sp2,
                                            const float* __restrict__ b_sp2,
                                            const float* __restrict__ w_ff,
                                            const float* __restrict__ b_ff){
    __shared__ __align__(16) float comb[4][2*DIM];   // 32KB
    __shared__ float lg[4][3];
    __shared__ float sw[4][2];
    int t = threadIdx.x, warp = t >> 5, lane = t & 31;
    int b0 = blockIdx.y * 4;
    int slot = blockIdx.x * 8 + warp;
    const float4* w4 = (const float4*)(w_ff + (size_t)slot * 2048);

    // prologue (pre-sync): span logits (sp_h complete since ctxgemm) + w_ff half-A prefetch
    for (int task = warp; task < 12; task += 8){
        int bb = task / 3;
        int j = task - bb * 3;
        const float4* sp = (const float4*)&g_sp_h[b0 + bb][0];
        const float4* wp = (const float4*)(w_sp2 + j*HID);
        float s = 0.f;
        #pragma unroll
        for (int i = lane; i < 128; i += 32){
            float4 a = sp[i], w = wp[i];
            s += a.x*w.x + a.y*w.y + a.z*w.z + a.w*w.w;
        }
        #pragma unroll
        for (int o = 16; o > 0; o >>= 1) s += __shfl_xor_sync(0xffffffffu, s, o);
        if (lane == 0) lg[bb][j] = s + b_sp2[j];
    }
    __syncthreads();
    if (t < 4){
        float a = lg[t][0], b2 = lg[t][1], c = lg[t][2];
        float m = fmaxf(a, fmaxf(b2, c));
        float ea = expf(a-m), eb = expf(b2-m), ec = expf(c-m);
        float inv = 1.0f / (ea + eb + ec);
        sw[t][0] = eb*inv; sw[t][1] = ec*inv;
    }
    float4 wregA[8];
    #pragma unroll
    for (int ii = 0; ii < 8; ii++) wregA[ii] = w4[lane + ii*32];

    cudaGridDependencySynchronize();   // wait: g_pool_feat from scorepool
    __syncthreads();

    for (int idx = t; idx < 4 * 2 * DIM; idx += 256){
        int bb = idx >> 11, k = idx & 2047;
        comb[bb][k] = (k < DIM) ? g_pool_feat[0][b0+bb][k] * sw[bb][0]
                                : g_pool_feat[1][b0+bb][k-DIM] * sw[bb][1];
    }
    __syncthreads();

    float acc[4] = {};
    #pragma unroll
    for (int ii = 0; ii < 8; ii++){
        int i = lane + ii*32;
        float4 w = wregA[ii];
        #pragma unroll
        for (int bb = 0; bb < 4; bb++){
            float4 c = *(const float4*)&comb[bb][i*4];
            acc[bb] += w.x*c.x + w.y*c.y + w.z*c.z + w.w*c.w;
        }
    }
    float4 wregB[8];
    #pragma unroll
    for (int ii = 0; ii < 8; ii++) wregB[ii] = w4[lane + (8 + ii)*32];
    #pragma unroll
    for (int ii = 0; ii < 8; ii++){
        int i = lane + (8 + ii)*32;
        float4 w = wregB[ii];
        #pragma unroll
        for (int bb = 0; bb < 4; bb++){
            float4 c = *(const float4*)&comb[bb][i*4];
            acc[bb] += w.x*c.x + w.y*c.y + w.z*c.z + w.w*c.w;
        }
    }
    #pragma unroll
    for (int bb = 0; bb < 4; bb++){
        float s = acc[bb];
        #pragma unroll
        for (int o = 16; o > 0; o >>= 1) s += __shfl_xor_sync(0xffffffffu, s, o);
        if (lane == 0) g_fused_raw[b0+bb][slot] = gelu_exact(s + b_ff[slot]);
    }
    cudaTriggerProgrammaticLaunchCompletion();
}

// ---------------- K6: LN + gate GEMV + fg (PDL both ways) --------------------------
__global__ void __launch_bounds__(256) k_gate(const float* __restrict__ ln_ff_g,
                                              const float* __restrict__ ln_ff_b,
                                              const float* __restrict__ w_gate,
                                              const float* __restrict__ b_gate){
    __shared__ __align__(16) float fr[4][DIM];   // 16KB
    __shared__ float mu_s[4], rstd_s[4];
    int t = threadIdx.x, warp = t >> 5, lane = t & 31;
    int b0 = blockIdx.y * 4;
    int slot = blockIdx.x * 8 + warp;

    // prologue: w_gate prefetch (input — safe pre-sync)
    const float4* w4 = (const float4*)(w_gate + (size_t)slot * 1024);
    float4 wreg[8];
    #pragma unroll
    for (int ii = 0; ii < 8; ii++) wreg[ii] = w4[lane + ii*32];

    cudaGridDependencySynchronize();   // wait: g_fused_raw from k_ff

    for (int idx = t; idx < 4 * DIM; idx += 256)
        fr[idx >> 10][idx & 1023] = g_fused_raw[b0 + (idx >> 10)][idx & 1023];
    __syncthreads();

    if (warp < 4){
        float sum = 0.f, ss = 0.f;
        #pragma unroll
        for (int i = lane; i < 256; i += 32){
            float4 v = *(const float4*)&fr[warp][i*4];
            sum += v.x + v.y + v.z + v.w;
            ss  += v.x*v.x + v.y*v.y + v.z*v.z + v.w*v.w;
        }
        #pragma unroll
        for (int o = 16; o > 0; o >>= 1){
            sum += __shfl_xor_sync(0xffffffffu, sum, o);
            ss  += __shfl_xor_sync(0xffffffffu, ss, o);
        }
        if (lane == 0){
            float mu = sum * (1.0f/1024.0f);
            float var = ss * (1.0f/1024.0f) - mu*mu;
            mu_s[warp] = mu; rstd_s[warp] = rsqrtf(var + 1e-5f);
        }
    }
    __syncthreads();

    for (int idx = t; idx < 4 * DIM; idx += 256){
        int bb = idx >> 10, k = idx & 1023;
        fr[bb][k] = (fr[bb][k] - mu_s[bb]) * rstd_s[bb] * ln_ff_g[k] + ln_ff_b[k];
    }
    __syncthreads();

    float acc[4] = {};
    #pragma unroll
    for (int ii = 0; ii < 8; ii++){
        int i = lane + ii*32;
        float4 w = wreg[ii];
        #pragma unroll
        for (int bb = 0; bb < 4; bb++){
            float4 c = *(const float4*)&fr[bb][i*4];
            acc[bb] += w.x*c.x + w.y*c.y + w.z*c.z + w.w*c.w;
        }
    }
    #pragma unroll
    for (int bb = 0; bb < 4; bb++){
        float s = acc[bb];
        #pragma unroll
        for (int o = 16; o > 0; o >>= 1) s += __shfl_xor_sync(0xffffffffu, s, o);
        if (lane == 0){
            float gate = 1.0f / (1.0f + expf(-(s + b_gate[slot])));
            g_fg[b0+bb][slot] = fr[bb][slot] * gate;
        }
    }
    cudaTriggerProgrammaticLaunchCompletion();
}

// ---------------- K7: big pass — output = LN(features + fg[b]) (PDL secondary) -----
__global__ void __launch_bounds__(256) k_bigln(const float* __restrict__ f,
                                               const float* __restrict__ ln_g,
                                               const float* __restrict__ ln_b,
                                               float* __restrict__ out){
    int warp = threadIdx.x >> 5, lane = threadIdx.x & 31;
    int row = blockIdx.x * 8 + warp;
    int b = row & 15;
    const float4* x4 = (const float4*)(f + (size_t)row * DIM);

    // prologue: stream this row's features (bulk of the read) pre-sync
    float4 v[8];
    #pragma unroll
    for (int i = 0; i < 8; i++) v[i] = x4[lane + i*32];

    cudaGridDependencySynchronize();   // wait: g_fg from k_gate

    const float4* fg4 = (const float4*)(&g_fg[b][0]);
    float sum = 0.f, ss = 0.f;
    #pragma unroll
    for (int i = 0; i < 8; i++){
        float4 c = fg4[lane + i*32];
        float4 tv = v[i];
        tv.x += c.x; tv.y += c.y; tv.z += c.z; tv.w += c.w;
        v[i] = tv;
        sum += tv.x + tv.y + tv.z + tv.w;
        ss  += tv.x*tv.x + tv.y*tv.y + tv.z*tv.z + tv.w*tv.w;
    }
    #pragma unroll
    for (int o = 16; o > 0; o >>= 1){
        sum += __shfl_xor_sync(0xffffffffu, sum, o);
        ss  += __shfl_xor_sync(0xffffffffu, ss, o);
    }
    float mu = sum * (1.0f/1024.0f);
    float var = ss * (1.0f/1024.0f) - mu*mu;
    float rstd = rsqrtf(var + 1e-5f);
    float4* o4 = (float4*)(out + (size_t)row * DIM);
    const float4* g4 = (const float4*)ln_g;
    const float4* b4 = (const float4*)ln_b;
    #pragma unroll
    for (int i = 0; i < 8; i++){
        float4 g = g4[lane + i*32], be = b4[lane + i*32], tv = v[i], r;
        r.x = (tv.x - mu)*rstd*g.x + be.x;
        r.y = (tv.y - mu)*rstd*g.y + be.y;
        r.z = (tv.z - mu)*rstd*g.z + be.z;
        r.w = (tv.w - mu)*rstd*g.w + be.w;
        o4[lane + i*32] = r;
    }
}

// ---------------- K8: attention weights fill ----------------------------------------
__global__ void k_aw(float* __restrict__ aw){
    aw[blockIdx.x * 256 + threadIdx.x] = 1.0f / 4096.0f;
}

// ---------------- launcher -----------------------------------------------------------
extern "C" void kernel_launch(void* const* d_in, const int* in_sizes, int n_in,
                              void* d_out, int out_size){
    const float* features = (const float*)d_in[0];
    const float* w_sp1    = (const float*)d_in[1];
    const float* b_sp1    = (const float*)d_in[2];
    const float* w_sp2    = (const float*)d_in[3];
    const float* b_sp2    = (const float*)d_in[4];
    const float* w_rs1    = (const float*)d_in[5];
    const float* b_rs1    = (const float*)d_in[6];
    const float* w_rs2    = (const float*)d_in[7];
    const float* b_rs2    = (const float*)d_in[8];
    const float* decay_l  = (const float*)d_in[9];
    const float* decay_g  = (const float*)d_in[10];
    const float* w_ff     = (const float*)d_in[11];
    const float* b_ff     = (const float*)d_in[12];
    const float* ln_ff_g  = (const float*)d_in[13];
    const float* ln_ff_b  = (const float*)d_in[14];
    const float* w_gate   = (const float*)d_in[15];
    const float* b_gate   = (const float*)d_in[16];
    const float* ln_g     = (const float*)d_in[17];
    const float* ln_b     = (const float*)d_in[18];
    float* out = (float*)d_out;
    float* out_aw = out + (size_t)SEQ * BATCH * DIM;

    static cudaStream_t s_side = nullptr;
    static cudaEvent_t ev_fork = nullptr, ev_join = nullptr;
    if (s_side == nullptr){
        cudaStreamCreateWithFlags(&s_side, cudaStreamNonBlocking);
        cudaEventCreateWithFlags(&ev_fork, cudaEventDisableTiming);
        cudaEventCreateWithFlags(&ev_join, cudaEventDisableTiming);
    }

    cudaLaunchAttribute pa[1];
    pa[0].id = cudaLaunchAttributeProgrammaticStreamSerialization;
    pa[0].val.programmaticStreamSerializationAllowed = 1;

    // fork: compute-bound hist GEMM + aw fill overlap the memory-bound mean pass
    cudaEventRecord(ev_fork, 0);
    cudaStreamWaitEvent(s_side, ev_fork, 0);
    k_histgemm<<<dim3(8, 8, 2), 256, 0, s_side>>>(features, w_rs1);
    k_aw<<<256, 256, 0, s_side>>>(out_aw);
    cudaEventRecord(ev_join, s_side);

    // main chain with PDL overlap at each boundary
    k_partial<<<dim3(64, 32), 256>>>(features);

    {
        cudaLaunchConfig_t c{}; c.gridDim = dim3(64); c.blockDim = dim3(256);
        c.stream = 0; c.attrs = pa; c.numAttrs = 1;
        cudaLaunchKernelEx(&c, k_ctxfin);
    }

    cudaStreamWaitEvent(0, ev_join, 0);
    k_ctxgemm<<<dim3(128, 2), 256>>>(w_sp1, b_sp1, w_rs1, b_rs1);

    {
        cudaLaunchConfig_t c{}; c.gridDim = dim3(16, 2); c.blockDim = dim3(1024);
        c.stream = 0; c.attrs = pa; c.numAttrs = 1;
        cudaLaunchKernelEx(&c, k_scorepool, features, w_rs2, b_rs2, decay_l, decay_g);
    }
    {
        cudaLaunchConfig_t c{}; c.gridDim = dim3(128, 4); c.blockDim = dim3(256);
        c.stream = 0; c.attrs = pa; c.numAttrs = 1;
        cudaLaunchKernelEx(&c, k_ff, w_sp2, b_sp2, w_ff, b_ff);
    }
    {
        cudaLaunchConfig_t c{}; c.gridDim = dim3(128, 4); c.blockDim = dim3(256);
        c.stream = 0; c.attrs = pa; c.numAttrs = 1;
        cudaLaunchKernelEx(&c, k_gate, ln_ff_g, ln_ff_b, w_gate, b_gate);
    }
    {
        cudaLaunchConfig_t c{}; c.gridDim = dim3(8192); c.blockDim = dim3(256);
        c.stream = 0; c.attrs = pa; c.numAttrs = 1;
        cudaLaunchKernelEx(&c, k_bigln, features, ln_g, ln_b, out);
    }
}

// round 10
// speedup vs baseline: 1.0701x; 1.0209x over previous
#include <cuda_runtime.h>
#include <math.h>

#define SEQ   4096
#define BATCH 16
#define DIM   1024
#define HID   512
#define LL    32
#define BD    (BATCH*DIM)   // 16384

// ---------------- scratch ---------------------------------------------------------
__device__ float g_partial[32][BD];
__device__ unsigned int g_cnt[64];            // zero-init; reset by last block each launch
__device__ float g_ctx[BATCH][DIM];
__device__ float g_sp_h[BATCH][HID];
__device__ float g_ctx_part[BATCH][HID];
__device__ float g_hist_pre[2][LL*BATCH][HID];
__device__ float g_pool_feat[2][BATCH][DIM];
__device__ float g_fused_raw[BATCH][DIM];
__device__ float g_fg[BATCH][DIM];

__device__ __forceinline__ float gelu_exact(float x){
    return 0.5f * x * (1.0f + erff(x * 0.70710678118654752440f));
}

// ---------------- K1: partial sums + last-block ctx finalize ------------------------
__global__ void __launch_bounds__(256) k_partial(const float* __restrict__ f){
    __shared__ bool is_last;
    int col = blockIdx.x * 256 + threadIdx.x;
    int sy  = blockIdx.y;
    const float* p = f + (size_t)sy * 128 * BD + col;
    float s = 0.f;
    #pragma unroll 8
    for (int i = 0; i < 128; i++) s += p[(size_t)i * BD];
    g_partial[sy][col] = s;

    // last block per column-chunk finalizes ctx
    __threadfence();
    __syncthreads();
    if (threadIdx.x == 0){
        unsigned int v = atomicAdd(&g_cnt[blockIdx.x], 1u);
        is_last = (v == 31u);
    }
    __syncthreads();
    if (is_last){
        float s2 = 0.f;
        #pragma unroll
        for (int j = 0; j < 32; j++) s2 += g_partial[j][col];
        g_ctx[col >> 10][col & 1023] = s2 * (1.0f/4096.0f);
        if (threadIdx.x == 0) g_cnt[blockIdx.x] = 0u;   // reset for next graph replay
    }
}

// ---------------- K2: hist GEMM (M=512,N=512,K=1024) x2 pools ----------------------
__global__ void __launch_bounds__(256) k_histgemm(const float* __restrict__ f,
                                                  const float* __restrict__ w_rs1){
    __shared__ __align__(16) float As[16][68];
    __shared__ __align__(16) float Bs[16][68];
    int pool = blockIdx.z;
    int m0 = blockIdx.y * 64, n0 = blockIdx.x * 64;
    int t = threadIdx.x;
    int lrow = t >> 2;
    int kq   = (t & 3) * 4;

    int m = m0 + lrow;
    size_t aoff = (pool == 0)
        ? (size_t)4064 * BD + (size_t)m * 1024
        : (size_t)(m >> 4) * 128 * BD + (size_t)(m & 15) * 1024;
    const float* aptr = f + aoff;
    const float* bptr = w_rs1 + (size_t)(n0 + lrow) * 2048;

    int tx = t & 15, ty = t >> 4;
    float acc[4][4] = {};

    for (int k0 = 0; k0 < 1024; k0 += 16){
        float4 av = *(const float4*)(aptr + k0 + kq);
        float4 bv = *(const float4*)(bptr + k0 + kq);
        __syncthreads();
        As[kq+0][lrow]=av.x; As[kq+1][lrow]=av.y; As[kq+2][lrow]=av.z; As[kq+3][lrow]=av.w;
        Bs[kq+0][lrow]=bv.x; Bs[kq+1][lrow]=bv.y; Bs[kq+2][lrow]=bv.z; Bs[kq+3][lrow]=bv.w;
        __syncthreads();
        #pragma unroll
        for (int kk = 0; kk < 16; kk++){
            float4 a = *(const float4*)&As[kk][ty*4];
            float4 b = *(const float4*)&Bs[kk][tx*4];
            acc[0][0] += a.x*b.x; acc[0][1] += a.x*b.y; acc[0][2] += a.x*b.z; acc[0][3] += a.x*b.w;
            acc[1][0] += a.y*b.x; acc[1][1] += a.y*b.y; acc[1][2] += a.y*b.z; acc[1][3] += a.y*b.w;
            acc[2][0] += a.z*b.x; acc[2][1] += a.z*b.y; acc[2][2] += a.z*b.z; acc[2][3] += a.z*b.w;
            acc[3][0] += a.w*b.x; acc[3][1] += a.w*b.y; acc[3][2] += a.w*b.z; acc[3][3] += a.w*b.w;
        }
    }
    #pragma unroll
    for (int i = 0; i < 4; i++)
        #pragma unroll
        for (int j = 0; j < 4; j++)
            g_hist_pre[pool][m0 + ty*4 + i][n0 + tx*4 + j] = acc[i][j];
}

// ---------------- K3: ctx MLPs (batch-reuse GEMV, 4 batches, 512 blocks) -----------
__global__ void __launch_bounds__(256) k_ctxgemm(const float* __restrict__ w_sp1,
                                                 const float* __restrict__ b_sp1,
                                                 const float* __restrict__ w_rs1,
                                                 const float* __restrict__ b_rs1){
    __shared__ __align__(16) float ctxs[4][DIM];   // 16KB
    int t = threadIdx.x, warp = t >> 5, lane = t & 31;
    int b0 = blockIdx.y * 4;

    for (int idx = t; idx < 4 * DIM; idx += 256)
        ctxs[idx >> 10][idx & 1023] = g_ctx[b0 + (idx >> 10)][idx & 1023];
    __syncthreads();

    int slot = blockIdx.x * 8 + warp;
    const float4* w4 = (slot < 512)
        ? (const float4*)(w_sp1 + (size_t)slot * 1024)
        : (const float4*)(w_rs1 + (size_t)(slot - 512) * 2048 + 1024);

    float4 wreg[8];
    #pragma unroll
    for (int ii = 0; ii < 8; ii++) wreg[ii] = w4[lane + ii*32];

    float acc[4] = {};
    #pragma unroll
    for (int ii = 0; ii < 8; ii++){
        int i = lane + ii*32;
        float4 w = wreg[ii];
        #pragma unroll
        for (int bb = 0; bb < 4; bb++){
            float4 c = *(const float4*)&ctxs[bb][i*4];
            acc[bb] += w.x*c.x + w.y*c.y + w.z*c.z + w.w*c.w;
        }
    }
    #pragma unroll
    for (int bb = 0; bb < 4; bb++){
        float s = acc[bb];
        #pragma unroll
        for (int o = 16; o > 0; o >>= 1) s += __shfl_xor_sync(0xffffffffu, s, o);
        if (lane == 0){
            if (slot < 512) g_sp_h[b0 + bb][slot] = gelu_exact(s + b_sp1[slot]);
            else            g_ctx_part[b0 + bb][slot - 512] = s + b_rs1[slot - 512];
        }
    }
}

// ---------------- K4: scores + decay softmax + pooled feature (fused) --------------
__global__ void __launch_bounds__(1024) k_scorepool(const float* __restrict__ f,
                                                    const float* __restrict__ w_rs2,
                                                    const float* __restrict__ b_rs2,
                                                    const float* __restrict__ decay_l,
                                                    const float* __restrict__ decay_g){
    int b = blockIdx.x, pool = blockIdx.y;
    int t = threadIdx.x, warp = t >> 5, lane = t & 31;
    __shared__ float wgt[LL];

    {
        const float4* hp = (const float4*)&g_hist_pre[pool][warp*16 + b][0];
        const float4* cp = (const float4*)&g_ctx_part[b][0];
        const float4* wp = (const float4*)w_rs2;
        float s = 0.f;
        #pragma unroll
        for (int i = lane; i < 128; i += 32){
            float4 h = hp[i], c = cp[i], w = wp[i];
            s += gelu_exact(h.x + c.x) * w.x + gelu_exact(h.y + c.y) * w.y
               + gelu_exact(h.z + c.z) * w.z + gelu_exact(h.w + c.w) * w.w;
        }
        #pragma unroll
        for (int o = 16; o > 0; o >>= 1) s += __shfl_xor_sync(0xffffffffu, s, o);
        if (lane == 0) wgt[warp] = s + b_rs2[0];
    }
    __syncthreads();

    if (warp == 0){
        float dec = (pool == 0) ? decay_l[0] : decay_g[0];
        float tv = wgt[lane] + logf(powf(dec, (float)(LL - 1 - lane)) + 1e-8f);
        float mx = tv;
        #pragma unroll
        for (int o = 16; o > 0; o >>= 1) mx = fmaxf(mx, __shfl_xor_sync(0xffffffffu, mx, o));
        float e = expf(tv - mx);
        float ssum = e;
        #pragma unroll
        for (int o = 16; o > 0; o >>= 1) ssum += __shfl_xor_sync(0xffffffffu, ssum, o);
        wgt[lane] = e / ssum;
    }
    __syncthreads();

    int d = t;
    float acc = 0.f;
    #pragma unroll
    for (int l = 0; l < LL; l++){
        size_t off = (pool == 0) ? (size_t)(4064 + l) * BD : (size_t)l * 128 * BD;
        acc += wgt[l] * f[off + (size_t)b*1024 + d];
    }
    g_pool_feat[pool][b][d] = acc;
}

// ---------------- K5: span softmax + fused MLP GEMV (batch-reuse) -------------------
__global__ void __launch_bounds__(256) k_ff(const float* __restrict__ w_sp2,
                                            const float* __restrict__ b_sp2,
                                            const float* __restrict__ w_ff,
                                            const float* __restrict__ b_ff){
    __shared__ __align__(16) float comb[4][2*DIM];   // 32KB
    __shared__ float lg[4][3];
    __shared__ float sw[4][2];
    int t = threadIdx.x, warp = t >> 5, lane = t & 31;
    int b0 = blockIdx.y * 4;

    for (int task = warp; task < 12; task += 8){
        int bb = task / 3;
        int j = task - bb * 3;
        const float4* sp = (const float4*)&g_sp_h[b0 + bb][0];
        const float4* wp = (const float4*)(w_sp2 + j*HID);
        float s = 0.f;
        #pragma unroll
        for (int i = lane; i < 128; i += 32){
            float4 a = sp[i], w = wp[i];
            s += a.x*w.x + a.y*w.y + a.z*w.z + a.w*w.w;
        }
        #pragma unroll
        for (int o = 16; o > 0; o >>= 1) s += __shfl_xor_sync(0xffffffffu, s, o);
        if (lane == 0) lg[bb][j] = s + b_sp2[j];
    }
    __syncthreads();
    if (t < 4){
        float a = lg[t][0], b2 = lg[t][1], c = lg[t][2];
        float m = fmaxf(a, fmaxf(b2, c));
        float ea = expf(a-m), eb = expf(b2-m), ec = expf(c-m);
        float inv = 1.0f / (ea + eb + ec);
        sw[t][0] = eb*inv; sw[t][1] = ec*inv;
    }
    __syncthreads();

    for (int idx = t; idx < 4 * 2 * DIM; idx += 256){
        int bb = idx >> 11, k = idx & 2047;
        comb[bb][k] = (k < DIM) ? g_pool_feat[0][b0+bb][k] * sw[bb][0]
                                : g_pool_feat[1][b0+bb][k-DIM] * sw[bb][1];
    }
    __syncthreads();

    int slot = blockIdx.x * 8 + warp;
    const float4* w4 = (const float4*)(w_ff + (size_t)slot * 2048);
    float acc[4] = {};
    #pragma unroll
    for (int half = 0; half < 2; half++){
        float4 wreg[8];
        #pragma unroll
        for (int ii = 0; ii < 8; ii++) wreg[ii] = w4[lane + (half*8 + ii)*32];
        #pragma unroll
        for (int ii = 0; ii < 8; ii++){
            int i = lane + (half*8 + ii)*32;
            float4 w = wreg[ii];
            #pragma unroll
            for (int bb = 0; bb < 4; bb++){
                float4 c = *(const float4*)&comb[bb][i*4];
                acc[bb] += w.x*c.x + w.y*c.y + w.z*c.z + w.w*c.w;
            }
        }
    }
    #pragma unroll
    for (int bb = 0; bb < 4; bb++){
        float s = acc[bb];
        #pragma unroll
        for (int o = 16; o > 0; o >>= 1) s += __shfl_xor_sync(0xffffffffu, s, o);
        if (lane == 0) g_fused_raw[b0+bb][slot] = gelu_exact(s + b_ff[slot]);
    }
}

// ---------------- K6: LN(fused_raw) + gate GEMV + fg (fused, batch-reuse) ----------
__global__ void __launch_bounds__(256) k_gate(const float* __restrict__ ln_ff_g,
                                              const float* __restrict__ ln_ff_b,
                                              const float* __restrict__ w_gate,
                                              const float* __restrict__ b_gate){
    __shared__ __align__(16) float fr[4][DIM];   // 16KB
    __shared__ float mu_s[4], rstd_s[4];
    int t = threadIdx.x, warp = t >> 5, lane = t & 31;
    int b0 = blockIdx.y * 4;

    for (int idx = t; idx < 4 * DIM; idx += 256)
        fr[idx >> 10][idx & 1023] = g_fused_raw[b0 + (idx >> 10)][idx & 1023];
    __syncthreads();

    if (warp < 4){
        float sum = 0.f, ss = 0.f;
        #pragma unroll
        for (int i = lane; i < 256; i += 32){
            float4 v = *(const float4*)&fr[warp][i*4];
            sum += v.x + v.y + v.z + v.w;
            ss  += v.x*v.x + v.y*v.y + v.z*v.z + v.w*v.w;
        }
        #pragma unroll
        for (int o = 16; o > 0; o >>= 1){
            sum += __shfl_xor_sync(0xffffffffu, sum, o);
            ss  += __shfl_xor_sync(0xffffffffu, ss, o);
        }
        if (lane == 0){
            float mu = sum * (1.0f/1024.0f);
            float var = ss * (1.0f/1024.0f) - mu*mu;
            mu_s[warp] = mu; rstd_s[warp] = rsqrtf(var + 1e-5f);
        }
    }
    __syncthreads();

    for (int idx = t; idx < 4 * DIM; idx += 256){
        int bb = idx >> 10, k = idx & 1023;
        fr[bb][k] = (fr[bb][k] - mu_s[bb]) * rstd_s[bb] * ln_ff_g[k] + ln_ff_b[k];
    }
    __syncthreads();

    int slot = blockIdx.x * 8 + warp;
    const float4* w4 = (const float4*)(w_gate + (size_t)slot * 1024);
    float acc[4] = {};
    #pragma unroll
    for (int i = lane; i < 256; i += 32){
        float4 w = w4[i];
        #pragma unroll
        for (int bb = 0; bb < 4; bb++){
            float4 c = *(const float4*)&fr[bb][i*4];
            acc[bb] += w.x*c.x + w.y*c.y + w.z*c.z + w.w*c.w;
        }
    }
    #pragma unroll
    for (int bb = 0; bb < 4; bb++){
        float s = acc[bb];
        #pragma unroll
        for (int o = 16; o > 0; o >>= 1) s += __shfl_xor_sync(0xffffffffu, s, o);
        if (lane == 0){
            float gate = 1.0f / (1.0f + expf(-(s + b_gate[slot])));
            g_fg[b0+bb][slot] = fr[bb][slot] * gate;
        }
    }
}

// ---------------- K7: big pass — output = LN(features + fg[b]) ----------------------
__global__ void __launch_bounds__(256) k_bigln(const float* __restrict__ f,
                                               const float* __restrict__ ln_g,
                                               const float* __restrict__ ln_b,
                                               float* __restrict__ out){
    int warp = threadIdx.x >> 5, lane = threadIdx.x & 31;
    int row = blockIdx.x * 8 + warp;
    int b = row & 15;
    const float4* x4  = (const float4*)(f + (size_t)row * DIM);
    const float4* fg4 = (const float4*)(&g_fg[b][0]);
    float4 v[8];
    float sum = 0.f, ss = 0.f;
    #pragma unroll
    for (int i = 0; i < 8; i++){
        float4 a = x4[lane + i*32];
        float4 c = fg4[lane + i*32];
        float4 tv;
        tv.x = a.x + c.x; tv.y = a.y + c.y; tv.z = a.z + c.z; tv.w = a.w + c.w;
        v[i] = tv;
        sum += tv.x + tv.y + tv.z + tv.w;
        ss  += tv.x*tv.x + tv.y*tv.y + tv.z*tv.z + tv.w*tv.w;
    }
    #pragma unroll
    for (int o = 16; o > 0; o >>= 1){
        sum += __shfl_xor_sync(0xffffffffu, sum, o);
        ss  += __shfl_xor_sync(0xffffffffu, ss, o);
    }
    float mu = sum * (1.0f/1024.0f);
    float var = ss * (1.0f/1024.0f) - mu*mu;
    float rstd = rsqrtf(var + 1e-5f);
    float4* o4 = (float4*)(out + (size_t)row * DIM);
    const float4* g4 = (const float4*)ln_g;
    const float4* b4 = (const float4*)ln_b;
    #pragma unroll
    for (int i = 0; i < 8; i++){
        float4 g = g4[lane + i*32], be = b4[lane + i*32], tv = v[i], r;
        r.x = (tv.x - mu)*rstd*g.x + be.x;
        r.y = (tv.y - mu)*rstd*g.y + be.y;
        r.z = (tv.z - mu)*rstd*g.z + be.z;
        r.w = (tv.w - mu)*rstd*g.w + be.w;
        o4[lane + i*32] = r;
    }
}

// ---------------- K8: attention weights fill -----------------------------------------
__global__ void k_aw(float* __restrict__ aw){
    aw[blockIdx.x * 256 + threadIdx.x] = 1.0f / 4096.0f;
}

// ---------------- launcher ------------------------------------------------------------
extern "C" void kernel_launch(void* const* d_in, const int* in_sizes, int n_in,
                              void* d_out, int out_size){
    const float* features = (const float*)d_in[0];
    const float* w_sp1    = (const float*)d_in[1];
    const float* b_sp1    = (const float*)d_in[2];
    const float* w_sp2    = (const float*)d_in[3];
    const float* b_sp2    = (const float*)d_in[4];
    const float* w_rs1    = (const float*)d_in[5];
    const float* b_rs1    = (const float*)d_in[6];
    const float* w_rs2    = (const float*)d_in[7];
    const float* b_rs2    = (const float*)d_in[8];
    const float* decay_l  = (const float*)d_in[9];
    const float* decay_g  = (const float*)d_in[10];
    const float* w_ff     = (const float*)d_in[11];
    const float* b_ff     = (const float*)d_in[12];
    const float* ln_ff_g  = (const float*)d_in[13];
    const float* ln_ff_b  = (const float*)d_in[14];
    const float* w_gate   = (const float*)d_in[15];
    const float* b_gate   = (const float*)d_in[16];
    const float* ln_g     = (const float*)d_in[17];
    const float* ln_b     = (const float*)d_in[18];
    float* out = (float*)d_out;
    float* out_aw = out + (size_t)SEQ * BATCH * DIM;

    static cudaStream_t s_side = nullptr;
    static cudaEvent_t ev_fork = nullptr, ev_join = nullptr;
    if (s_side == nullptr){
        cudaStreamCreateWithFlags(&s_side, cudaStreamNonBlocking);
        cudaEventCreateWithFlags(&ev_fork, cudaEventDisableTiming);
        cudaEventCreateWithFlags(&ev_join, cudaEventDisableTiming);
    }

    // fork: compute-bound hist GEMM + aw fill overlap the memory-bound mean pass
    cudaEventRecord(ev_fork, 0);
    cudaStreamWaitEvent(s_side, ev_fork, 0);
    k_histgemm<<<dim3(8, 8, 2), 256, 0, s_side>>>(features, w_rs1);
    k_aw<<<256, 256, 0, s_side>>>(out_aw);
    cudaEventRecord(ev_join, s_side);

    // main chain (ctxfin folded into k_partial via last-block reduction)
    k_partial<<<dim3(64, 32), 256>>>(features);
    k_ctxgemm<<<dim3(128, 4), 256>>>(w_sp1, b_sp1, w_rs1, b_rs1);

    cudaStreamWaitEvent(0, ev_join, 0);
    k_scorepool<<<dim3(16, 2), 1024>>>(features, w_rs2, b_rs2, decay_l, decay_g);
    k_ff<<<dim3(128, 4), 256>>>(w_sp2, b_sp2, w_ff, b_ff);
    k_gate<<<dim3(128, 4), 256>>>(ln_ff_g, ln_ff_b, w_gate, b_gate);
    k_bigln<<<8192, 256>>>(features, ln_g, ln_b, out);
}

// round 11
// speedup vs baseline: 1.0814x; 1.0106x over previous
#include <cuda_runtime.h>
#include <math.h>

#define SEQ   4096
#define BATCH 16
#define DIM   1024
#define HID   512
#define LL    32
#define BD    (BATCH*DIM)   // 16384

// ---------------- scratch ---------------------------------------------------------
__device__ float g_partial[32][BD];
__device__ unsigned int g_cnt[64];            // zero-init; reset by last block each launch
__device__ float g_ctx[BATCH][DIM];
__device__ float g_sp_h[BATCH][HID];
__device__ float g_ctx_part[BATCH][HID];
__device__ float g_hist_pre[2][LL*BATCH][HID];
__device__ float g_pool_feat[2][BATCH][DIM];
__device__ float g_fused_raw[BATCH][DIM];
__device__ float g_fg[BATCH][DIM];

__device__ __forceinline__ float gelu_exact(float x){
    return 0.5f * x * (1.0f + erff(x * 0.70710678118654752440f));
}

// ---------------- K1: partial sums + last-block ctx finalize ------------------------
__global__ void __launch_bounds__(256) k_partial(const float* __restrict__ f){
    __shared__ bool is_last;
    int col = blockIdx.x * 256 + threadIdx.x;
    int sy  = blockIdx.y;
    const float* p = f + (size_t)sy * 128 * BD + col;
    float s = 0.f;
    #pragma unroll 8
    for (int i = 0; i < 128; i++) s += p[(size_t)i * BD];
    g_partial[sy][col] = s;

    __threadfence();
    __syncthreads();
    if (threadIdx.x == 0){
        unsigned int v = atomicAdd(&g_cnt[blockIdx.x], 1u);
        is_last = (v == 31u);
    }
    __syncthreads();
    if (is_last){
        float s2 = 0.f;
        #pragma unroll
        for (int j = 0; j < 32; j++) s2 += g_partial[j][col];
        g_ctx[col >> 10][col & 1023] = s2 * (1.0f/4096.0f);
        if (threadIdx.x == 0) g_cnt[blockIdx.x] = 0u;   // reset for next graph replay
    }
}

// ---------------- K2: hist GEMM (M=512,N=512,K=1024) x2 pools ----------------------
__global__ void __launch_bounds__(256) k_histgemm(const float* __restrict__ f,
                                                  const float* __restrict__ w_rs1){
    __shared__ __align__(16) float As[16][68];
    __shared__ __align__(16) float Bs[16][68];
    int pool = blockIdx.z;
    int m0 = blockIdx.y * 64, n0 = blockIdx.x * 64;
    int t = threadIdx.x;
    int lrow = t >> 2;
    int kq   = (t & 3) * 4;

    int m = m0 + lrow;
    size_t aoff = (pool == 0)
        ? (size_t)4064 * BD + (size_t)m * 1024
        : (size_t)(m >> 4) * 128 * BD + (size_t)(m & 15) * 1024;
    const float* aptr = f + aoff;
    const float* bptr = w_rs1 + (size_t)(n0 + lrow) * 2048;

    int tx = t & 15, ty = t >> 4;
    float acc[4][4] = {};

    for (int k0 = 0; k0 < 1024; k0 += 16){
        float4 av = *(const float4*)(aptr + k0 + kq);
        float4 bv = *(const float4*)(bptr + k0 + kq);
        __syncthreads();
        As[kq+0][lrow]=av.x; As[kq+1][lrow]=av.y; As[kq+2][lrow]=av.z; As[kq+3][lrow]=av.w;
        Bs[kq+0][lrow]=bv.x; Bs[kq+1][lrow]=bv.y; Bs[kq+2][lrow]=bv.z; Bs[kq+3][lrow]=bv.w;
        __syncthreads();
        #pragma unroll
        for (int kk = 0; kk < 16; kk++){
            float4 a = *(const float4*)&As[kk][ty*4];
            float4 b = *(const float4*)&Bs[kk][tx*4];
            acc[0][0] += a.x*b.x; acc[0][1] += a.x*b.y; acc[0][2] += a.x*b.z; acc[0][3] += a.x*b.w;
            acc[1][0] += a.y*b.x; acc[1][1] += a.y*b.y; acc[1][2] += a.y*b.z; acc[1][3] += a.y*b.w;
            acc[2][0] += a.z*b.x; acc[2][1] += a.z*b.y; acc[2][2] += a.z*b.z; acc[2][3] += a.z*b.w;
            acc[3][0] += a.w*b.x; acc[3][1] += a.w*b.y; acc[3][2] += a.w*b.z; acc[3][3] += a.w*b.w;
        }
    }
    #pragma unroll
    for (int i = 0; i < 4; i++)
        #pragma unroll
        for (int j = 0; j < 4; j++)
            g_hist_pre[pool][m0 + ty*4 + i][n0 + tx*4 + j] = acc[i][j];
}

// ---------------- K3: ctx MLPs (batch-reuse GEMV, 8 batches/block) ------------------
__global__ void __launch_bounds__(256) k_ctxgemm(const float* __restrict__ w_sp1,
                                                 const float* __restrict__ b_sp1,
                                                 const float* __restrict__ w_rs1,
                                                 const float* __restrict__ b_rs1){
    __shared__ __align__(16) float ctxs[8][DIM];   // 32KB
    int t = threadIdx.x, warp = t >> 5, lane = t & 31;
    int b0 = blockIdx.y * 8;

    for (int idx = t; idx < 8 * DIM; idx += 256)
        ctxs[idx >> 10][idx & 1023] = g_ctx[b0 + (idx >> 10)][idx & 1023];
    __syncthreads();

    int slot = blockIdx.x * 8 + warp;
    const float4* w4 = (slot < 512)
        ? (const float4*)(w_sp1 + (size_t)slot * 1024)
        : (const float4*)(w_rs1 + (size_t)(slot - 512) * 2048 + 1024);

    float acc[8] = {};
    #pragma unroll
    for (int i = lane; i < 256; i += 32){
        float4 w = w4[i];
        #pragma unroll
        for (int bb = 0; bb < 8; bb++){
            float4 c = *(const float4*)&ctxs[bb][i*4];
            acc[bb] += w.x*c.x + w.y*c.y + w.z*c.z + w.w*c.w;
        }
    }
    #pragma unroll
    for (int bb = 0; bb < 8; bb++){
        float s = acc[bb];
        #pragma unroll
        for (int o = 16; o > 0; o >>= 1) s += __shfl_xor_sync(0xffffffffu, s, o);
        if (lane == 0){
            if (slot < 512) g_sp_h[b0 + bb][slot] = gelu_exact(s + b_sp1[slot]);
            else            g_ctx_part[b0 + bb][slot - 512] = s + b_rs1[slot - 512];
        }
    }
}

// ---------------- K4: scores + decay softmax + pooled feature (fused) --------------
__global__ void __launch_bounds__(1024) k_scorepool(const float* __restrict__ f,
                                                    const float* __restrict__ w_rs2,
                                                    const float* __restrict__ b_rs2,
                                                    const float* __restrict__ decay_l,
                                                    const float* __restrict__ decay_g){
    int b = blockIdx.x, pool = blockIdx.y;
    int t = threadIdx.x, warp = t >> 5, lane = t & 31;
    __shared__ float wgt[LL];

    {
        const float4* hp = (const float4*)&g_hist_pre[pool][warp*16 + b][0];
        const float4* cp = (const float4*)&g_ctx_part[b][0];
        const float4* wp = (const float4*)w_rs2;
        float s = 0.f;
        #pragma unroll
        for (int i = lane; i < 128; i += 32){
            float4 h = hp[i], c = cp[i], w = wp[i];
            s += gelu_exact(h.x + c.x) * w.x + gelu_exact(h.y + c.y) * w.y
               + gelu_exact(h.z + c.z) * w.z + gelu_exact(h.w + c.w) * w.w;
        }
        #pragma unroll
        for (int o = 16; o > 0; o >>= 1) s += __shfl_xor_sync(0xffffffffu, s, o);
        if (lane == 0) wgt[warp] = s + b_rs2[0];
    }
    __syncthreads();

    if (warp == 0){
        float dec = (pool == 0) ? decay_l[0] : decay_g[0];
        float tv = wgt[lane] + logf(powf(dec, (float)(LL - 1 - lane)) + 1e-8f);
        float mx = tv;
        #pragma unroll
        for (int o = 16; o > 0; o >>= 1) mx = fmaxf(mx, __shfl_xor_sync(0xffffffffu, mx, o));
        float e = expf(tv - mx);
        float ssum = e;
        #pragma unroll
        for (int o = 16; o > 0; o >>= 1) ssum += __shfl_xor_sync(0xffffffffu, ssum, o);
        wgt[lane] = e / ssum;
    }
    __syncthreads();

    int d = t;
    float acc = 0.f;
    #pragma unroll
    for (int l = 0; l < LL; l++){
        size_t off = (pool == 0) ? (size_t)(4064 + l) * BD : (size_t)l * 128 * BD;
        acc += wgt[l] * f[off + (size_t)b*1024 + d];
    }
    g_pool_feat[pool][b][d] = acc;
}

// ---------------- K5: span softmax + fused MLP GEMV (batch-reuse) -------------------
__global__ void __launch_bounds__(256) k_ff(const float* __restrict__ w_sp2,
                                            const float* __restrict__ b_sp2,
                                            const float* __restrict__ w_ff,
                                            const float* __restrict__ b_ff){
    __shared__ __align__(16) float comb[4][2*DIM];   // 32KB
    __shared__ float lg[4][3];
    __shared__ float sw[4][2];
    int t = threadIdx.x, warp = t >> 5, lane = t & 31;
    int b0 = blockIdx.y * 4;

    for (int task = warp; task < 12; task += 8){
        int bb = task / 3;
        int j = task - bb * 3;
        const float4* sp = (const float4*)&g_sp_h[b0 + bb][0];
        const float4* wp = (const float4*)(w_sp2 + j*HID);
        float s = 0.f;
        #pragma unroll
        for (int i = lane; i < 128; i += 32){
            float4 a = sp[i], w = wp[i];
            s += a.x*w.x + a.y*w.y + a.z*w.z + a.w*w.w;
        }
        #pragma unroll
        for (int o = 16; o > 0; o >>= 1) s += __shfl_xor_sync(0xffffffffu, s, o);
        if (lane == 0) lg[bb][j] = s + b_sp2[j];
    }
    __syncthreads();
    if (t < 4){
        float a = lg[t][0], b2 = lg[t][1], c = lg[t][2];
        float m = fmaxf(a, fmaxf(b2, c));
        float ea = expf(a-m), eb = expf(b2-m), ec = expf(c-m);
        float inv = 1.0f / (ea + eb + ec);
        sw[t][0] = eb*inv; sw[t][1] = ec*inv;
    }
    __syncthreads();

    for (int idx = t; idx < 4 * 2 * DIM; idx += 256){
        int bb = idx >> 11, k = idx & 2047;
        comb[bb][k] = (k < DIM) ? g_pool_feat[0][b0+bb][k] * sw[bb][0]
                                : g_pool_feat[1][b0+bb][k-DIM] * sw[bb][1];
    }
    __syncthreads();

    int slot = blockIdx.x * 8 + warp;
    const float4* w4 = (const float4*)(w_ff + (size_t)slot * 2048);
    float acc[4] = {};
    #pragma unroll
    for (int i = lane; i < 512; i += 32){
        float4 w = w4[i];
        #pragma unroll
        for (int bb = 0; bb < 4; bb++){
            float4 c = *(const float4*)&comb[bb][i*4];
            acc[bb] += w.x*c.x + w.y*c.y + w.z*c.z + w.w*c.w;
        }
    }
    #pragma unroll
    for (int bb = 0; bb < 4; bb++){
        float s = acc[bb];
        #pragma unroll
        for (int o = 16; o > 0; o >>= 1) s += __shfl_xor_sync(0xffffffffu, s, o);
        if (lane == 0) g_fused_raw[b0+bb][slot] = gelu_exact(s + b_ff[slot]);
    }
}

// ---------------- K6: LN(fused_raw) + gate GEMV + fg (fused, batch-reuse) ----------
__global__ void __launch_bounds__(256) k_gate(const float* __restrict__ ln_ff_g,
                                              const float* __restrict__ ln_ff_b,
                                              const float* __restrict__ w_gate,
                                              const float* __restrict__ b_gate){
    __shared__ __align__(16) float fr[4][DIM];   // 16KB
    __shared__ float mu_s[4], rstd_s[4];
    int t = threadIdx.x, warp = t >> 5, lane = t & 31;
    int b0 = blockIdx.y * 4;

    for (int idx = t; idx < 4 * DIM; idx += 256)
        fr[idx >> 10][idx & 1023] = g_fused_raw[b0 + (idx >> 10)][idx & 1023];
    __syncthreads();

    if (warp < 4){
        float sum = 0.f, ss = 0.f;
        #pragma unroll
        for (int i = lane; i < 256; i += 32){
            float4 v = *(const float4*)&fr[warp][i*4];
            sum += v.x + v.y + v.z + v.w;
            ss  += v.x*v.x + v.y*v.y + v.z*v.z + v.w*v.w;
        }
        #pragma unroll
        for (int o = 16; o > 0; o >>= 1){
            sum += __shfl_xor_sync(0xffffffffu, sum, o);
            ss  += __shfl_xor_sync(0xffffffffu, ss, o);
        }
        if (lane == 0){
            float mu = sum * (1.0f/1024.0f);
            float var = ss * (1.0f/1024.0f) - mu*mu;
            mu_s[warp] = mu; rstd_s[warp] = rsqrtf(var + 1e-5f);
        }
    }
    __syncthreads();

    for (int idx = t; idx < 4 * DIM; idx += 256){
        int bb = idx >> 10, k = idx & 1023;
        fr[bb][k] = (fr[bb][k] - mu_s[bb]) * rstd_s[bb] * ln_ff_g[k] + ln_ff_b[k];
    }
    __syncthreads();

    int slot = blockIdx.x * 8 + warp;
    const float4* w4 = (const float4*)(w_gate + (size_t)slot * 1024);
    float acc[4] = {};
    #pragma unroll
    for (int i = lane; i < 256; i += 32){
        float4 w = w4[i];
        #pragma unroll
        for (int bb = 0; bb < 4; bb++){
            float4 c = *(const float4*)&fr[bb][i*4];
            acc[bb] += w.x*c.x + w.y*c.y + w.z*c.z + w.w*c.w;
        }
    }
    #pragma unroll
    for (int bb = 0; bb < 4; bb++){
        float s = acc[bb];
        #pragma unroll
        for (int o = 16; o > 0; o >>= 1) s += __shfl_xor_sync(0xffffffffu, s, o);
        if (lane == 0){
            float gate = 1.0f / (1.0f + expf(-(s + b_gate[slot])));
            g_fg[b0+bb][slot] = fr[bb][slot] * gate;
        }
    }
}

// ---------------- K7: big pass — output = LN(features + fg[b]) ----------------------
// __stwt: write-through stores — output never re-read; keep L2 for the read stream.
__global__ void __launch_bounds__(256) k_bigln(const float* __restrict__ f,
                                               const float* __restrict__ ln_g,
                                               const float* __restrict__ ln_b,
                                               float* __restrict__ out){
    int warp = threadIdx.x >> 5, lane = threadIdx.x & 31;
    int row = blockIdx.x * 8 + warp;
    int b = row & 15;
    const float4* x4  = (const float4*)(f + (size_t)row * DIM);
    const float4* fg4 = (const float4*)(&g_fg[b][0]);
    float4 v[8];
    float sum = 0.f, ss = 0.f;
    #pragma unroll
    for (int i = 0; i < 8; i++){
        float4 a = x4[lane + i*32];
        float4 c = fg4[lane + i*32];
        float4 tv;
        tv.x = a.x + c.x; tv.y = a.y + c.y; tv.z = a.z + c.z; tv.w = a.w + c.w;
        v[i] = tv;
        sum += tv.x + tv.y + tv.z + tv.w;
        ss  += tv.x*tv.x + tv.y*tv.y + tv.z*tv.z + tv.w*tv.w;
    }
    #pragma unroll
    for (int o = 16; o > 0; o >>= 1){
        sum += __shfl_xor_sync(0xffffffffu, sum, o);
        ss  += __shfl_xor_sync(0xffffffffu, ss, o);
    }
    float mu = sum * (1.0f/1024.0f);
    float var = ss * (1.0f/1024.0f) - mu*mu;
    float rstd = rsqrtf(var + 1e-5f);
    float4* o4 = (float4*)(out + (size_t)row * DIM);
    const float4* g4 = (const float4*)ln_g;
    const float4* b4 = (const float4*)ln_b;
    #pragma unroll
    for (int i = 0; i < 8; i++){
        float4 g = g4[lane + i*32], be = b4[lane + i*32], tv = v[i], r;
        r.x = (tv.x - mu)*rstd*g.x + be.x;
        r.y = (tv.y - mu)*rstd*g.y + be.y;
        r.z = (tv.z - mu)*rstd*g.z + be.z;
        r.w = (tv.w - mu)*rstd*g.w + be.w;
        __stwt(&o4[lane + i*32], r);
    }
}

// ---------------- K8: attention weights fill -----------------------------------------
__global__ void k_aw(float* __restrict__ aw){
    __stwt(&aw[blockIdx.x * 256 + threadIdx.x], 1.0f / 4096.0f);
}

// ---------------- launcher ------------------------------------------------------------
extern "C" void kernel_launch(void* const* d_in, const int* in_sizes, int n_in,
                              void* d_out, int out_size){
    const float* features = (const float*)d_in[0];
    const float* w_sp1    = (const float*)d_in[1];
    const float* b_sp1    = (const float*)d_in[2];
    const float* w_sp2    = (const float*)d_in[3];
    const float* b_sp2    = (const float*)d_in[4];
    const float* w_rs1    = (const float*)d_in[5];
    const float* b_rs1    = (const float*)d_in[6];
    const float* w_rs2    = (const float*)d_in[7];
    const float* b_rs2    = (const float*)d_in[8];
    const float* decay_l  = (const float*)d_in[9];
    const float* decay_g  = (const float*)d_in[10];
    const float* w_ff     = (const float*)d_in[11];
    const float* b_ff     = (const float*)d_in[12];
    const float* ln_ff_g  = (const float*)d_in[13];
    const float* ln_ff_b  = (const float*)d_in[14];
    const float* w_gate   = (const float*)d_in[15];
    const float* b_gate   = (const float*)d_in[16];
    const float* ln_g     = (const float*)d_in[17];
    const float* ln_b     = (const float*)d_in[18];
    float* out = (float*)d_out;
    float* out_aw = out + (size_t)SEQ * BATCH * DIM;

    static cudaStream_t s_side = nullptr;
    static cudaEvent_t ev_fork = nullptr, ev_join = nullptr;
    if (s_side == nullptr){
        cudaStreamCreateWithFlags(&s_side, cudaStreamNonBlocking);
        cudaEventCreateWithFlags(&ev_fork, cudaEventDisableTiming);
        cudaEventCreateWithFlags(&ev_join, cudaEventDisableTiming);
    }

    // fork: compute-bound hist GEMM + aw fill overlap the memory-bound mean pass
    cudaEventRecord(ev_fork, 0);
    cudaStreamWaitEvent(s_side, ev_fork, 0);
    k_histgemm<<<dim3(8, 8, 2), 256, 0, s_side>>>(features, w_rs1);
    k_aw<<<256, 256, 0, s_side>>>(out_aw);
    cudaEventRecord(ev_join, s_side);

    // main chain (ctxfin folded into k_partial via last-block reduction)
    k_partial<<<dim3(64, 32), 256>>>(features);
    k_ctxgemm<<<dim3(128, 2), 256>>>(w_sp1, b_sp1, w_rs1, b_rs1);

    cudaStreamWaitEvent(0, ev_join, 0);
    k_scorepool<<<dim3(16, 2), 1024>>>(features, w_rs2, b_rs2, decay_l, decay_g);
    k_ff<<<dim3(128, 4), 256>>>(w_sp2, b_sp2, w_ff, b_ff);
    k_gate<<<dim3(128, 4), 256>>>(ln_ff_g, ln_ff_b, w_gate, b_gate);
    k_bigln<<<8192, 256>>>(features, ln_g, ln_b, out);
}

// round 12
// speedup vs baseline: 1.1467x; 1.0604x over previous
#include <cuda_runtime.h>
#include <math.h>

#define SEQ   4096
#define BATCH 16
#define DIM   1024
#define HID   512
#define LL    32
#define BD    (BATCH*DIM)   // 16384

// ---------------- scratch ---------------------------------------------------------
__device__ float g_partial[32][BD];
__device__ unsigned int g_cnt[64];            // zero-init; reset by last block each launch
__device__ float g_ctx[BATCH][DIM];
__device__ float g_sp_h[BATCH][HID];
__device__ float g_ctx_part[BATCH][HID];
__device__ float g_hist_pre[2][LL*BATCH][HID];
__device__ float g_pool_feat[2][BATCH][DIM];
__device__ float g_fused_raw[BATCH][DIM];
__device__ float g_fg[BATCH][DIM];

__device__ __forceinline__ float gelu_exact(float x){
    return 0.5f * x * (1.0f + erff(x * 0.70710678118654752440f));
}

// ---------------- K1: partial sums + last-block ctx finalize ------------------------
__global__ void __launch_bounds__(256) k_partial(const float* __restrict__ f){
    __shared__ bool is_last;
    int col = blockIdx.x * 256 + threadIdx.x;
    int sy  = blockIdx.y;
    const float* p = f + (size_t)sy * 128 * BD + col;
    float s = 0.f;
    #pragma unroll 8
    for (int i = 0; i < 128; i++) s += p[(size_t)i * BD];
    g_partial[sy][col] = s;

    __threadfence();
    __syncthreads();
    if (threadIdx.x == 0){
        unsigned int v = atomicAdd(&g_cnt[blockIdx.x], 1u);
        is_last = (v == 31u);
    }
    __syncthreads();
    if (is_last){
        float s2 = 0.f;
        #pragma unroll
        for (int j = 0; j < 32; j++) s2 += g_partial[j][col];
        g_ctx[col >> 10][col & 1023] = s2 * (1.0f/4096.0f);
        if (threadIdx.x == 0) g_cnt[blockIdx.x] = 0u;   // reset for next graph replay
    }
}

// ---------------- K2: hist GEMM (M=512,N=512,K=1024) x2 pools ----------------------
__global__ void __launch_bounds__(256) k_histgemm(const float* __restrict__ f,
                                                  const float* __restrict__ w_rs1){
    __shared__ __align__(16) float As[16][68];
    __shared__ __align__(16) float Bs[16][68];
    int pool = blockIdx.z;
    int m0 = blockIdx.y * 64, n0 = blockIdx.x * 64;
    int t = threadIdx.x;
    int lrow = t >> 2;
    int kq   = (t & 3) * 4;

    int m = m0 + lrow;
    size_t aoff = (pool == 0)
        ? (size_t)4064 * BD + (size_t)m * 1024
        : (size_t)(m >> 4) * 128 * BD + (size_t)(m & 15) * 1024;
    const float* aptr = f + aoff;
    const float* bptr = w_rs1 + (size_t)(n0 + lrow) * 2048;

    int tx = t & 15, ty = t >> 4;
    float acc[4][4] = {};

    for (int k0 = 0; k0 < 1024; k0 += 16){
        float4 av = *(const float4*)(aptr + k0 + kq);
        float4 bv = *(const float4*)(bptr + k0 + kq);
        __syncthreads();
        As[kq+0][lrow]=av.x; As[kq+1][lrow]=av.y; As[kq+2][lrow]=av.z; As[kq+3][lrow]=av.w;
        Bs[kq+0][lrow]=bv.x; Bs[kq+1][lrow]=bv.y; Bs[kq+2][lrow]=bv.z; Bs[kq+3][lrow]=bv.w;
        __syncthreads();
        #pragma unroll
        for (int kk = 0; kk < 16; kk++){
            float4 a = *(const float4*)&As[kk][ty*4];
            float4 b = *(const float4*)&Bs[kk][tx*4];
            acc[0][0] += a.x*b.x; acc[0][1] += a.x*b.y; acc[0][2] += a.x*b.z; acc[0][3] += a.x*b.w;
            acc[1][0] += a.y*b.x; acc[1][1] += a.y*b.y; acc[1][2] += a.y*b.z; acc[1][3] += a.y*b.w;
            acc[2][0] += a.z*b.x; acc[2][1] += a.z*b.y; acc[2][2] += a.z*b.z; acc[2][3] += a.z*b.w;
            acc[3][0] += a.w*b.x; acc[3][1] += a.w*b.y; acc[3][2] += a.w*b.z; acc[3][3] += a.w*b.w;
        }
    }
    #pragma unroll
    for (int i = 0; i < 4; i++)
        #pragma unroll
        for (int j = 0; j < 4; j++)
            g_hist_pre[pool][m0 + ty*4 + i][n0 + tx*4 + j] = acc[i][j];
}

// ---------------- K3: ctx MLPs (batch-reuse GEMV, 8 batches, float4 staging) --------
__global__ void __launch_bounds__(256) k_ctxgemm(const float* __restrict__ w_sp1,
                                                 const float* __restrict__ b_sp1,
                                                 const float* __restrict__ w_rs1,
                                                 const float* __restrict__ b_rs1){
    __shared__ __align__(16) float ctxs[8][DIM];   // 32KB
    int t = threadIdx.x, warp = t >> 5, lane = t & 31;
    int b0 = blockIdx.y * 8;

    // vectorized staging: 2048 float4 / 256 threads = 8 independent 16B loads
    {
        const float4* src = (const float4*)&g_ctx[b0][0];
        float4* dst = (float4*)&ctxs[0][0];
        #pragma unroll
        for (int ii = 0; ii < 8; ii++) dst[t + ii*256] = src[t + ii*256];
    }
    __syncthreads();

    int slot = blockIdx.x * 8 + warp;
    const float4* w4 = (slot < 512)
        ? (const float4*)(w_sp1 + (size_t)slot * 1024)
        : (const float4*)(w_rs1 + (size_t)(slot - 512) * 2048 + 1024);

    float acc[8] = {};
    #pragma unroll
    for (int i = lane; i < 256; i += 32){
        float4 w = w4[i];
        #pragma unroll
        for (int bb = 0; bb < 8; bb++){
            float4 c = *(const float4*)&ctxs[bb][i*4];
            acc[bb] += w.x*c.x + w.y*c.y + w.z*c.z + w.w*c.w;
        }
    }
    #pragma unroll
    for (int bb = 0; bb < 8; bb++){
        float s = acc[bb];
        #pragma unroll
        for (int o = 16; o > 0; o >>= 1) s += __shfl_xor_sync(0xffffffffu, s, o);
        if (lane == 0){
            if (slot < 512) g_sp_h[b0 + bb][slot] = gelu_exact(s + b_sp1[slot]);
            else            g_ctx_part[b0 + bb][slot - 512] = s + b_rs1[slot - 512];
        }
    }
}

// ---------------- K4: scores + decay softmax + pooled feature (fused) --------------
__global__ void __launch_bounds__(1024) k_scorepool(const float* __restrict__ f,
                                                    const float* __restrict__ w_rs2,
                                                    const float* __restrict__ b_rs2,
                                                    const float* __restrict__ decay_l,
                                                    const float* __restrict__ decay_g){
    int b = blockIdx.x, pool = blockIdx.y;
    int t = threadIdx.x, warp = t >> 5, lane = t & 31;
    __shared__ float wgt[LL];

    {
        const float4* hp = (const float4*)&g_hist_pre[pool][warp*16 + b][0];
        const float4* cp = (const float4*)&g_ctx_part[b][0];
        const float4* wp = (const float4*)w_rs2;
        float s = 0.f;
        #pragma unroll
        for (int i = lane; i < 128; i += 32){
            float4 h = hp[i], c = cp[i], w = wp[i];
            s += gelu_exact(h.x + c.x) * w.x + gelu_exact(h.y + c.y) * w.y
               + gelu_exact(h.z + c.z) * w.z + gelu_exact(h.w + c.w) * w.w;
        }
        #pragma unroll
        for (int o = 16; o > 0; o >>= 1) s += __shfl_xor_sync(0xffffffffu, s, o);
        if (lane == 0) wgt[warp] = s + b_rs2[0];
    }
    __syncthreads();

    if (warp == 0){
        float dec = (pool == 0) ? decay_l[0] : decay_g[0];
        float tv = wgt[lane] + logf(powf(dec, (float)(LL - 1 - lane)) + 1e-8f);
        float mx = tv;
        #pragma unroll
        for (int o = 16; o > 0; o >>= 1) mx = fmaxf(mx, __shfl_xor_sync(0xffffffffu, mx, o));
        float e = expf(tv - mx);
        float ssum = e;
        #pragma unroll
        for (int o = 16; o > 0; o >>= 1) ssum += __shfl_xor_sync(0xffffffffu, ssum, o);
        wgt[lane] = e / ssum;
    }
    __syncthreads();

    int d = t;
    float acc = 0.f;
    #pragma unroll
    for (int l = 0; l < LL; l++){
        size_t off = (pool == 0) ? (size_t)(4064 + l) * BD : (size_t)l * 128 * BD;
        acc += wgt[l] * f[off + (size_t)b*1024 + d];
    }
    g_pool_feat[pool][b][d] = acc;
}

// ---------------- K5: span softmax + fused MLP GEMV (float4 staging) ----------------
__global__ void __launch_bounds__(256) k_ff(const float* __restrict__ w_sp2,
                                            const float* __restrict__ b_sp2,
                                            const float* __restrict__ w_ff,
                                            const float* __restrict__ b_ff){
    __shared__ __align__(16) float comb[4][2*DIM];   // 32KB
    __shared__ float lg[4][3];
    __shared__ float sw[4][2];
    int t = threadIdx.x, warp = t >> 5, lane = t & 31;
    int b0 = blockIdx.y * 4;

    for (int task = warp; task < 12; task += 8){
        int bb = task / 3;
        int j = task - bb * 3;
        const float4* sp = (const float4*)&g_sp_h[b0 + bb][0];
        const float4* wp = (const float4*)(w_sp2 + j*HID);
        float s = 0.f;
        #pragma unroll
        for (int i = lane; i < 128; i += 32){
            float4 a = sp[i], w = wp[i];
            s += a.x*w.x + a.y*w.y + a.z*w.z + a.w*w.w;
        }
        #pragma unroll
        for (int o = 16; o > 0; o >>= 1) s += __shfl_xor_sync(0xffffffffu, s, o);
        if (lane == 0) lg[bb][j] = s + b_sp2[j];
    }
    __syncthreads();
    if (t < 4){
        float a = lg[t][0], b2 = lg[t][1], c = lg[t][2];
        float m = fmaxf(a, fmaxf(b2, c));
        float ea = expf(a-m), eb = expf(b2-m), ec = expf(c-m);
        float inv = 1.0f / (ea + eb + ec);
        sw[t][0] = eb*inv; sw[t][1] = ec*inv;
    }
    __syncthreads();

    // vectorized staging: 2048 float4 / 256 threads = 8 loads; k<DIM boundary is float4-aligned
    {
        #pragma unroll
        for (int ii = 0; ii < 8; ii++){
            int idx4 = t + ii*256;               // float4 index within comb (0..2047)
            int bb = idx4 >> 9, k4 = idx4 & 511; // 512 float4 per comb row
            float4 v;
            float scale;
            if (k4 < 256){
                v = *(const float4*)&g_pool_feat[0][b0+bb][k4*4];
                scale = sw[bb][0];
            } else {
                v = *(const float4*)&g_pool_feat[1][b0+bb][(k4-256)*4];
                scale = sw[bb][1];
            }
            v.x *= scale; v.y *= scale; v.z *= scale; v.w *= scale;
            *(float4*)&comb[bb][k4*4] = v;
        }
    }
    __syncthreads();

    int slot = blockIdx.x * 8 + warp;
    const float4* w4 = (const float4*)(w_ff + (size_t)slot * 2048);
    float acc[4] = {};
    #pragma unroll
    for (int i = lane; i < 512; i += 32){
        float4 w = w4[i];
        #pragma unroll
        for (int bb = 0; bb < 4; bb++){
            float4 c = *(const float4*)&comb[bb][i*4];
            acc[bb] += w.x*c.x + w.y*c.y + w.z*c.z + w.w*c.w;
        }
    }
    #pragma unroll
    for (int bb = 0; bb < 4; bb++){
        float s = acc[bb];
        #pragma unroll
        for (int o = 16; o > 0; o >>= 1) s += __shfl_xor_sync(0xffffffffu, s, o);
        if (lane == 0) g_fused_raw[b0+bb][slot] = gelu_exact(s + b_ff[slot]);
    }
}

// ---------------- K6: LN(fused_raw) + gate GEMV + fg (float4 staging) ---------------
__global__ void __launch_bounds__(256) k_gate(const float* __restrict__ ln_ff_g,
                                              const float* __restrict__ ln_ff_b,
                                              const float* __restrict__ w_gate,
                                              const float* __restrict__ b_gate){
    __shared__ __align__(16) float fr[4][DIM];   // 16KB
    __shared__ float mu_s[4], rstd_s[4];
    int t = threadIdx.x, warp = t >> 5, lane = t & 31;
    int b0 = blockIdx.y * 4;

    // vectorized staging: 1024 float4 / 256 threads = 4 loads
    {
        const float4* src = (const float4*)&g_fused_raw[b0][0];
        float4* dst = (float4*)&fr[0][0];
        #pragma unroll
        for (int ii = 0; ii < 4; ii++) dst[t + ii*256] = src[t + ii*256];
    }
    __syncthreads();

    if (warp < 4){
        float sum = 0.f, ss = 0.f;
        #pragma unroll
        for (int i = lane; i < 256; i += 32){
            float4 v = *(const float4*)&fr[warp][i*4];
            sum += v.x + v.y + v.z + v.w;
            ss  += v.x*v.x + v.y*v.y + v.z*v.z + v.w*v.w;
        }
        #pragma unroll
        for (int o = 16; o > 0; o >>= 1){
            sum += __shfl_xor_sync(0xffffffffu, sum, o);
            ss  += __shfl_xor_sync(0xffffffffu, ss, o);
        }
        if (lane == 0){
            float mu = sum * (1.0f/1024.0f);
            float var = ss * (1.0f/1024.0f) - mu*mu;
            mu_s[warp] = mu; rstd_s[warp] = rsqrtf(var + 1e-5f);
        }
    }
    __syncthreads();

    // vectorized normalize: 1024 float4 / 256 threads = 4
    {
        const float4* g4 = (const float4*)ln_ff_g;
        const float4* be4 = (const float4*)ln_ff_b;
        #pragma unroll
        for (int ii = 0; ii < 4; ii++){
            int idx4 = t + ii*256;               // 0..1023
            int bb = idx4 >> 8, k4 = idx4 & 255; // 256 float4 per row
            float4 v = *(const float4*)&fr[bb][k4*4];
            float4 g = g4[k4], be = be4[k4];
            float mu = mu_s[bb], rstd = rstd_s[bb];
            v.x = (v.x - mu)*rstd*g.x + be.x;
            v.y = (v.y - mu)*rstd*g.y + be.y;
            v.z = (v.z - mu)*rstd*g.z + be.z;
            v.w = (v.w - mu)*rstd*g.w + be.w;
            *(float4*)&fr[bb][k4*4] = v;
        }
    }
    __syncthreads();

    int slot = blockIdx.x * 8 + warp;
    const float4* w4 = (const float4*)(w_gate + (size_t)slot * 1024);
    float acc[4] = {};
    #pragma unroll
    for (int i = lane; i < 256; i += 32){
        float4 w = w4[i];
        #pragma unroll
        for (int bb = 0; bb < 4; bb++){
            float4 c = *(const float4*)&fr[bb][i*4];
            acc[bb] += w.x*c.x + w.y*c.y + w.z*c.z + w.w*c.w;
        }
    }
    #pragma unroll
    for (int bb = 0; bb < 4; bb++){
        float s = acc[bb];
        #pragma unroll
        for (int o = 16; o > 0; o >>= 1) s += __shfl_xor_sync(0xffffffffu, s, o);
        if (lane == 0){
            float gate = 1.0f / (1.0f + expf(-(s + b_gate[slot])));
            g_fg[b0+bb][slot] = fr[bb][slot] * gate;
        }
    }
}

// ---------------- K7: big pass — output = LN(features + fg[b]) ----------------------
__global__ void __launch_bounds__(256) k_bigln(const float* __restrict__ f,
                                               const float* __restrict__ ln_g,
                                               const float* __restrict__ ln_b,
                                               float* __restrict__ out){
    int warp = threadIdx.x >> 5, lane = threadIdx.x & 31;
    int row = blockIdx.x * 8 + warp;
    int b = row & 15;
    const float4* x4  = (const float4*)(f + (size_t)row * DIM);
    const float4* fg4 = (const float4*)(&g_fg[b][0]);
    float4 v[8];
    float sum = 0.f, ss = 0.f;
    #pragma unroll
    for (int i = 0; i < 8; i++){
        float4 a = x4[lane + i*32];
        float4 c = fg4[lane + i*32];
        float4 tv;
        tv.x = a.x + c.x; tv.y = a.y + c.y; tv.z = a.z + c.z; tv.w = a.w + c.w;
        v[i] = tv;
        sum += tv.x + tv.y + tv.z + tv.w;
        ss  += tv.x*tv.x + tv.y*tv.y + tv.z*tv.z + tv.w*tv.w;
    }
    #pragma unroll
    for (int o = 16; o > 0; o >>= 1){
        sum += __shfl_xor_sync(0xffffffffu, sum, o);
        ss  += __shfl_xor_sync(0xffffffffu, ss, o);
    }
    float mu = sum * (1.0f/1024.0f);
    float var = ss * (1.0f/1024.0f) - mu*mu;
    float rstd = rsqrtf(var + 1e-5f);
    float4* o4 = (float4*)(out + (size_t)row * DIM);
    const float4* g4 = (const float4*)ln_g;
    const float4* b4 = (const float4*)ln_b;
    #pragma unroll
    for (int i = 0; i < 8; i++){
        float4 g = g4[lane + i*32], be = b4[lane + i*32], tv = v[i], r;
        r.x = (tv.x - mu)*rstd*g.x + be.x;
        r.y = (tv.y - mu)*rstd*g.y + be.y;
        r.z = (tv.z - mu)*rstd*g.z + be.z;
        r.w = (tv.w - mu)*rstd*g.w + be.w;
        __stwt(&o4[lane + i*32], r);
    }
}

// ---------------- K8: attention weights fill -----------------------------------------
__global__ void k_aw(float* __restrict__ aw){
    __stwt(&aw[blockIdx.x * 256 + threadIdx.x], 1.0f / 4096.0f);
}

// ---------------- launcher ------------------------------------------------------------
extern "C" void kernel_launch(void* const* d_in, const int* in_sizes, int n_in,
                              void* d_out, int out_size){
    const float* features = (const float*)d_in[0];
    const float* w_sp1    = (const float*)d_in[1];
    const float* b_sp1    = (const float*)d_in[2];
    const float* w_sp2    = (const float*)d_in[3];
    const float* b_sp2    = (const float*)d_in[4];
    const float* w_rs1    = (const float*)d_in[5];
    const float* b_rs1    = (const float*)d_in[6];
    const float* w_rs2    = (const float*)d_in[7];
    const float* b_rs2    = (const float*)d_in[8];
    const float* decay_l  = (const float*)d_in[9];
    const float* decay_g  = (const float*)d_in[10];
    const float* w_ff     = (const float*)d_in[11];
    const float* b_ff     = (const float*)d_in[12];
    const float* ln_ff_g  = (const float*)d_in[13];
    const float* ln_ff_b  = (const float*)d_in[14];
    const float* w_gate   = (const float*)d_in[15];
    const float* b_gate   = (const float*)d_in[16];
    const float* ln_g     = (const float*)d_in[17];
    const float* ln_b     = (const float*)d_in[18];
    float* out = (float*)d_out;
    float* out_aw = out + (size_t)SEQ * BATCH * DIM;

    static cudaStream_t s_side = nullptr;
    static cudaEvent_t ev_fork = nullptr, ev_join = nullptr;
    if (s_side == nullptr){
        cudaStreamCreateWithFlags(&s_side, cudaStreamNonBlocking);
        cudaEventCreateWithFlags(&ev_fork, cudaEventDisableTiming);
        cudaEventCreateWithFlags(&ev_join, cudaEventDisableTiming);
    }

    // fork: compute-bound hist GEMM + aw fill overlap the memory-bound mean pass
    cudaEventRecord(ev_fork, 0);
    cudaStreamWaitEvent(s_side, ev_fork, 0);
    k_histgemm<<<dim3(8, 8, 2), 256, 0, s_side>>>(features, w_rs1);
    k_aw<<<256, 256, 0, s_side>>>(out_aw);
    cudaEventRecord(ev_join, s_side);

    // main chain (ctxfin folded into k_partial via last-block reduction)
    k_partial<<<dim3(64, 32), 256>>>(features);
    k_ctxgemm<<<dim3(128, 2), 256>>>(w_sp1, b_sp1, w_rs1, b_rs1);

    cudaStreamWaitEvent(0, ev_join, 0);
    k_scorepool<<<dim3(16, 2), 1024>>>(features, w_rs2, b_rs2, decay_l, decay_g);
    k_ff<<<dim3(128, 4), 256>>>(w_sp2, b_sp2, w_ff, b_ff);
    k_gate<<<dim3(128, 4), 256>>>(ln_ff_g, ln_ff_b, w_gate, b_gate);
    k_bigln<<<8192, 256>>>(features, ln_g, ln_b, out);
}